// round 9
// baseline (speedup 1.0000x reference)
#include <cuda_runtime.h>
#include <cuda_fp16.h>

// Problem constants
#define B_ 4
#define L_ 2048
#define D_ 1024
#define H_ 16
#define HD_ 64
#define MROWS 8192      // B*L
#define N3D 3072        // 3*D

// ---------------- device scratch (static allocation only) ----------------
__device__ __align__(16) __half g_xh[MROWS * D_];
__device__ __align__(16) __half g_xl[MROWS * D_];
__device__ __align__(16) __half g_wqh[D_ * N3D];   // [K][N] layout
__device__ __align__(16) __half g_wql[D_ * N3D];
__device__ __align__(16) __half g_woh[D_ * D_];
__device__ __align__(16) __half g_wol[D_ * D_];
__device__ __align__(16) __half g_q_hi[64 * 2048 * 64];
__device__ __align__(16) __half g_q_lo[64 * 2048 * 64];
__device__ __align__(16) __half g_k_hi[64 * 2048 * 64];
__device__ __align__(16) __half g_k_lo[64 * 2048 * 64];
__device__ __align__(16) __half g_v_hi[64 * 2048 * 64];
__device__ __align__(16) __half g_v_lo[64 * 2048 * 64];
__device__ __align__(16) __half g_aoh[MROWS * D_];
__device__ __align__(16) __half g_aol[MROWS * D_];
__device__ __align__(16) float  g_cos[L_ * 32];
__device__ __align__(16) float  g_sin[L_ * 32];

// ---------------- PTX helpers ----------------
__device__ __forceinline__ void mma_fp16(float* d, const unsigned* a, unsigned b0, unsigned b1) {
    asm volatile(
        "mma.sync.aligned.m16n8k16.row.col.f32.f16.f16.f32 "
        "{%0,%1,%2,%3}, {%4,%5,%6,%7}, {%8,%9}, {%0,%1,%2,%3};\n"
        : "+f"(d[0]), "+f"(d[1]), "+f"(d[2]), "+f"(d[3])
        : "r"(a[0]), "r"(a[1]), "r"(a[2]), "r"(a[3]), "r"(b0), "r"(b1));
}
__device__ __forceinline__ void ldsm_x4(unsigned& r0, unsigned& r1, unsigned& r2, unsigned& r3, unsigned a) {
    asm volatile("ldmatrix.sync.aligned.m8n8.x4.shared.b16 {%0,%1,%2,%3}, [%4];\n"
                 : "=r"(r0), "=r"(r1), "=r"(r2), "=r"(r3) : "r"(a));
}
__device__ __forceinline__ void ldsm_x4t(unsigned& r0, unsigned& r1, unsigned& r2, unsigned& r3, unsigned a) {
    asm volatile("ldmatrix.sync.aligned.m8n8.x4.trans.shared.b16 {%0,%1,%2,%3}, [%4];\n"
                 : "=r"(r0), "=r"(r1), "=r"(r2), "=r"(r3) : "r"(a));
}
__device__ __forceinline__ void cp_async16(unsigned dst, const void* src) {
    asm volatile("cp.async.cg.shared.global [%0], [%1], 16;\n" :: "r"(dst), "l"(src));
}
__device__ __forceinline__ void cp_commit() { asm volatile("cp.async.commit_group;\n" ::: "memory"); }
template<int N> __device__ __forceinline__ void cp_wait() {
    asm volatile("cp.async.wait_group %0;\n" :: "n"(N) : "memory");
}
__device__ __forceinline__ unsigned pack2(__half a, __half b) {
    __half2 h = __halves2half2(a, b);
    return *reinterpret_cast<unsigned*>(&h);
}

// ---------------- x split (fp32 -> hi/lo halves) + fused RoPE table ----------------
__global__ void k_split_x(const float* __restrict__ src, int n4) {
    int i = blockIdx.x * blockDim.x + threadIdx.x;
    if (blockIdx.x < 256) {
        int idx = blockIdx.x * 256 + threadIdx.x;   // < 65536 = L_*32
        int l = idx >> 5, f = idx & 31;
        double invd = pow(10000.0, -(double)(2 * f) / 64.0);
        float invf = (float)invd;        // fp32 inv_freq matches jax value
        float ang = (float)l * invf;     // fp32 angle matches reference rounding
        double da = (double)ang;
        g_cos[idx] = (float)cos(da);
        g_sin[idx] = (float)sin(da);
    }
    if (i >= n4) return;
    float4 v = reinterpret_cast<const float4*>(src)[i];
    __half h0 = __float2half(v.x), h1 = __float2half(v.y);
    __half h2 = __float2half(v.z), h3 = __float2half(v.w);
    __half l0 = __float2half(v.x - __half2float(h0));
    __half l1 = __float2half(v.y - __half2float(h1));
    __half l2 = __float2half(v.z - __half2float(h2));
    __half l3 = __float2half(v.w - __half2float(h3));
    reinterpret_cast<__half2*>(g_xh)[2 * i]     = __halves2half2(h0, h1);
    reinterpret_cast<__half2*>(g_xh)[2 * i + 1] = __halves2half2(h2, h3);
    reinterpret_cast<__half2*>(g_xl)[2 * i]     = __halves2half2(l0, l1);
    reinterpret_cast<__half2*>(g_xl)[2 * i + 1] = __halves2half2(l2, l3);
}

// ---------------- weight split (keeps [K][N] layout) ----------------
__global__ void k_split_w(const float* __restrict__ src, int which, int n4) {
    __half* hi = (which == 1) ? g_wqh : g_woh;
    __half* lo = (which == 1) ? g_wql : g_wol;
    int i = blockIdx.x * blockDim.x + threadIdx.x;
    if (i >= n4) return;
    float4 v = reinterpret_cast<const float4*>(src)[i];
    __half h0 = __float2half(v.x), h1 = __float2half(v.y);
    __half h2 = __float2half(v.z), h3 = __float2half(v.w);
    __half l0 = __float2half(v.x - __half2float(h0));
    __half l1 = __float2half(v.y - __half2float(h1));
    __half l2 = __float2half(v.z - __half2float(h2));
    __half l3 = __float2half(v.w - __half2float(h3));
    reinterpret_cast<__half2*>(hi)[2 * i]     = __halves2half2(h0, h1);
    reinterpret_cast<__half2*>(hi)[2 * i + 1] = __halves2half2(h2, h3);
    reinterpret_cast<__half2*>(lo)[2 * i]     = __halves2half2(l0, l1);
    reinterpret_cast<__half2*>(lo)[2 * i + 1] = __halves2half2(l2, l3);
}

// ---------------- split-fp16 raw-mma GEMM, 512 threads, 256x128 tile, 3-stage ----------------
// which==0: A=x(split), B=Wqkv(split), fused epilogue: bias+rmsnorm+rope+split -> g_{q,k,v}_{hi,lo}
// which==1: A=attn_out(split), B=Wout(split), epilogue: bias -> Cext fp32
#define GA_LD 40
#define GB_LD 136
#define G_AL (256 * GA_LD)              // 10240 halfs
#define G_BH (2 * 256 * GA_LD)          // 20480
#define G_BLo (G_BH + 32 * GB_LD)       // 24832
#define G_STAGE (G_BH + 2 * 32 * GB_LD) // 29184 halfs per stage
#define GEMM_SMEM (3 * G_STAGE * 2)     // 175104 bytes (epilogue staging reuses this)

__device__ __forceinline__ void gemm_load_stage(unsigned smb, int s,
        const __half* Ah, const __half* Al, const __half* Bh, const __half* Bl,
        int m0, int n0, int k0, int N, int K, int tid) {
    unsigned sb = smb + (unsigned)(s * (G_STAGE * 2));
#pragma unroll
    for (int t = 0; t < 2; t++) {
        int c = tid + t * 512;              // 0..1023 chunks of A per array
        int ar = c >> 2, ac = (c & 3) * 8;
        unsigned da = sb + (unsigned)((ar * GA_LD + ac) * 2);
        cp_async16(da, Ah + (size_t)(m0 + ar) * K + k0 + ac);
        cp_async16(da + (unsigned)(G_AL * 2), Al + (size_t)(m0 + ar) * K + k0 + ac);
    }
    {
        int br = tid >> 4, bc = (tid & 15) * 8;   // 512 chunks of B per array
        unsigned db = sb + (unsigned)((G_BH + br * GB_LD + bc) * 2);
        cp_async16(db, Bh + (size_t)(k0 + br) * N + n0 + bc);
        cp_async16(db + (unsigned)((G_BLo - G_BH) * 2), Bl + (size_t)(k0 + br) * N + n0 + bc);
    }
}

__global__ __launch_bounds__(512, 1) void k_gemm(int which, const float* __restrict__ bias,
                                                 const float* __restrict__ qn_w,
                                                 const float* __restrict__ kn_w,
                                                 float* __restrict__ Cext,
                                                 int M, int N, int K) {
    extern __shared__ __align__(128) char sm_[];
    unsigned smb = (unsigned)__cvta_generic_to_shared(sm_);

    const __half* Ah = which ? g_aoh : g_xh;
    const __half* Al = which ? g_aol : g_xl;
    const __half* Bh = which ? g_woh : g_wqh;
    const __half* Bl = which ? g_wol : g_wql;

    int tid = threadIdx.x;
    int m0 = blockIdx.y * 256, n0 = blockIdx.x * 128;
    int wid = tid >> 5, lane = tid & 31;
    int wm = wid & 7, wn = wid >> 3;   // 8x2 warp grid; warp tile 32 rows x 64 cols

    float acc[2][8][4];                // [m16-tile][n8-tile][c-frag]
#pragma unroll
    for (int mi = 0; mi < 2; mi++)
#pragma unroll
        for (int g = 0; g < 8; g++)
#pragma unroll
            for (int r = 0; r < 4; r++) acc[mi][g][r] = 0.0f;

    gemm_load_stage(smb, 0, Ah, Al, Bh, Bl, m0, n0, 0,  N, K, tid); cp_commit();
    gemm_load_stage(smb, 1, Ah, Al, Bh, Bl, m0, n0, 32, N, K, tid); cp_commit();

    // ldmatrix lane addressing (constant per thread)
    int a_rofs = ((lane >> 3) & 1) * 8 + (lane & 7);   // row-within-16 provider
    int a_cofs = (lane >> 4) * 8;                      // k offset provider
    int b_rofs = ((lane >> 3) & 1) * 8 + (lane & 7);
    int b_cofs = ((lane >> 4) << 3);

    int niter = K / 32;
    for (int it = 0; it < niter; it++) {
        if (it < niter - 1) cp_wait<1>(); else cp_wait<0>();
        __syncthreads();
        int s = it - (it / 3) * 3;
        unsigned sb = smb + (unsigned)(s * (G_STAGE * 2));

#pragma unroll
        for (int kk = 0; kk < 32; kk += 16) {
            // A fragments: 2 m16-tiles, hi & lo
            unsigned ah[2][4], al[2][4];
#pragma unroll
            for (int mi = 0; mi < 2; mi++) {
                unsigned aaddr = sb + (unsigned)(((wm * 32 + mi * 16 + a_rofs) * GA_LD
                                                 + kk + a_cofs) * 2);
                ldsm_x4(ah[mi][0], ah[mi][1], ah[mi][2], ah[mi][3], aaddr);
                ldsm_x4(al[mi][0], al[mi][1], al[mi][2], al[mi][3],
                        aaddr + (unsigned)(G_AL * 2));
            }
            // B: 4 groups of n16, trans-ldmatrix from [k][n]
#pragma unroll
            for (int g = 0; g < 4; g++) {
                unsigned baddr = sb + (unsigned)((G_BH + (kk + b_rofs) * GB_LD
                                                  + wn * 64 + g * 16 + b_cofs) * 2);
                unsigned bh0, bh1, bh2, bh3, bl0, bl1, bl2, bl3;
                ldsm_x4t(bh0, bh1, bh2, bh3, baddr);
                ldsm_x4t(bl0, bl1, bl2, bl3, baddr + (unsigned)((G_BLo - G_BH) * 2));
#pragma unroll
                for (int mi = 0; mi < 2; mi++) {
                    mma_fp16(acc[mi][2 * g],     ah[mi], bh0, bh1);
                    mma_fp16(acc[mi][2 * g],     al[mi], bh0, bh1);
                    mma_fp16(acc[mi][2 * g],     ah[mi], bl0, bl1);
                    mma_fp16(acc[mi][2 * g + 1], ah[mi], bh2, bh3);
                    mma_fp16(acc[mi][2 * g + 1], al[mi], bh2, bh3);
                    mma_fp16(acc[mi][2 * g + 1], ah[mi], bl2, bl3);
                }
            }
        }
        if (it + 2 < niter) {
            int s2 = (it + 2) - ((it + 2) / 3) * 3;
            gemm_load_stage(smb, s2, Ah, Al, Bh, Bl, m0, n0, (it + 2) * 32, N, K, tid);
            cp_commit();
        }
    }

    // ---- epilogue: stage warp tile (32x64) to smem, one lane per row ----
    __syncthreads();                       // pipeline smem free for staging
    float* st = (float*)sm_ + (size_t)wid * (32 * 68);
    {
        int cr = lane >> 2, cc = (lane & 3) * 2;
#pragma unroll
        for (int mi = 0; mi < 2; mi++)
#pragma unroll
            for (int g = 0; g < 8; g++) {
                st[(mi * 16 + cr) * 68 + g * 8 + cc]     = acc[mi][g][0];
                st[(mi * 16 + cr) * 68 + g * 8 + cc + 1] = acc[mi][g][1];
                st[(mi * 16 + cr + 8) * 68 + g * 8 + cc]     = acc[mi][g][2];
                st[(mi * 16 + cr + 8) * 68 + g * 8 + cc + 1] = acc[mi][g][3];
            }
    }
    __syncwarp();

    int gr = m0 + wm * 32 + lane;          // global row (lane owns one row)
    int gn0 = n0 + wn * 64;                // global col base (64-aligned => single head/matrix)
    float* rp = st + lane * 68;

    if (which == 0) {
        int sel = gn0 >> 10;               // 0=Q, 1=K, 2=V
        int h = (gn0 & 1023) >> 6;
        int b = gr >> 11, l = gr & 2047;
        size_t dst = ((size_t)(b * 16 + h) * 2048 + l) * 64;
        __half *hi, *lo;
        if (sel == 0)      { hi = g_q_hi; lo = g_q_lo; }
        else if (sel == 1) { hi = g_k_hi; lo = g_k_lo; }
        else               { hi = g_v_hi; lo = g_v_lo; }

        if (sel == 2) {
#pragma unroll
            for (int c = 0; c < 64; c += 2) {
                float v0 = rp[c]     + bias[gn0 + c];
                float v1 = rp[c + 1] + bias[gn0 + c + 1];
                __half a0 = __float2half(v0), a1 = __float2half(v1);
                *(unsigned*)(hi + dst + c) = pack2(a0, a1);
                *(unsigned*)(lo + dst + c) = pack2(__float2half(v0 - __half2float(a0)),
                                                   __float2half(v1 - __half2float(a1)));
            }
        } else {
            const float* w = (sel == 0) ? qn_w : kn_w;
            float ss = 0.f;
#pragma unroll
            for (int c = 0; c < 64; c++) {
                float v = rp[c] + bias[gn0 + c];
                rp[c] = v;
                ss += v * v;
            }
            float rms = rsqrtf(ss * (1.0f / 64.0f) + 1e-6f);
            float qs = (sel == 0) ? 0.125f : 1.0f;   // fold attn scale into Q
#pragma unroll
            for (int c = 0; c < 32; c += 2) {
                float cv0 = g_cos[l * 32 + c],     sv0 = g_sin[l * 32 + c];
                float cv1 = g_cos[l * 32 + c + 1], sv1 = g_sin[l * 32 + c + 1];
                float t10 = rp[c]      * rms * w[c];
                float t11 = rp[c + 1]  * rms * w[c + 1];
                float t20 = rp[c + 32] * rms * w[c + 32];
                float t21 = rp[c + 33] * rms * w[c + 33];
                float o10 = (t10 * cv0 - t20 * sv0) * qs;
                float o11 = (t11 * cv1 - t21 * sv1) * qs;
                float o20 = (t10 * sv0 + t20 * cv0) * qs;
                float o21 = (t11 * sv1 + t21 * cv1) * qs;
                __half a0 = __float2half(o10), a1 = __float2half(o11);
                __half b0 = __float2half(o20), b1 = __float2half(o21);
                *(unsigned*)(hi + dst + c)      = pack2(a0, a1);
                *(unsigned*)(hi + dst + 32 + c) = pack2(b0, b1);
                *(unsigned*)(lo + dst + c)      = pack2(__float2half(o10 - __half2float(a0)),
                                                        __float2half(o11 - __half2float(a1)));
                *(unsigned*)(lo + dst + 32 + c) = pack2(__float2half(o20 - __half2float(b0)),
                                                        __float2half(o21 - __half2float(b1)));
            }
        }
    } else {
        float* dst = Cext + (size_t)gr * N + gn0;
#pragma unroll
        for (int c = 0; c < 64; c += 4) {
            float4 v;
            v.x = rp[c]     + bias[gn0 + c];
            v.y = rp[c + 1] + bias[gn0 + c + 1];
            v.z = rp[c + 2] + bias[gn0 + c + 2];
            v.w = rp[c + 3] + bias[gn0 + c + 3];
            *reinterpret_cast<float4*>(dst + c) = v;
        }
    }
}

// ---------------- FA2-style flash attention, register-resident, 2-stage, 2 CTAs/SM ----------------
#define ATT_LD 72
#define ATT_TILE (64 * ATT_LD)
#define ATT_STAGE (4 * ATT_TILE)
#define ATT_SMEM (2 * ATT_STAGE * 2)    // 73728 bytes -> two CTAs per SM

__device__ __forceinline__ void att_load_tile(unsigned smb, size_t gbase, int j, int s, int tid) {
    const __half* src0 = g_k_hi + gbase;
    const __half* src1 = g_k_lo + gbase;
    const __half* src2 = g_v_hi + gbase;
    const __half* src3 = g_v_lo + gbase;
#pragma unroll
    for (int t = 0; t < 2; t++) {
        int c = tid + t * 256;
        int row = c >> 3, col = (c & 7) * 8;
        size_t goff = (size_t)(j * 64 + row) * 64 + col;
        unsigned d = smb + (unsigned)((s * ATT_STAGE + row * ATT_LD + col) * 2);
        cp_async16(d,                                src0 + goff);
        cp_async16(d + (unsigned)(ATT_TILE * 2),     src1 + goff);
        cp_async16(d + (unsigned)(2 * ATT_TILE * 2), src2 + goff);
        cp_async16(d + (unsigned)(3 * ATT_TILE * 2), src3 + goff);
    }
}

__global__ __launch_bounds__(256, 2) void k_attn() {
    extern __shared__ __align__(128) char sm_[];
    unsigned smb = (unsigned)__cvta_generic_to_shared(sm_);

    int tid = threadIdx.x, lane = tid & 31, wid = tid >> 5;
    int bh = blockIdx.y;
    size_t gbase = (size_t)bh * (2048 * 64);
    int q0 = blockIdx.x * 128 + wid * 16;

    unsigned qf[2][4][4];
    {
        const __half* Qh = g_q_hi + gbase;
        const __half* Ql = g_q_lo + gbase;
        int r0 = q0 + (lane >> 2);
        int cb = (lane & 3) * 2;
#pragma unroll
        for (int kk = 0; kk < 4; kk++) {
            int c = kk * 16 + cb;
            qf[0][kk][0] = *(const unsigned*)(Qh + (size_t)r0 * 64 + c);
            qf[0][kk][1] = *(const unsigned*)(Qh + (size_t)(r0 + 8) * 64 + c);
            qf[0][kk][2] = *(const unsigned*)(Qh + (size_t)r0 * 64 + c + 8);
            qf[0][kk][3] = *(const unsigned*)(Qh + (size_t)(r0 + 8) * 64 + c + 8);
            qf[1][kk][0] = *(const unsigned*)(Ql + (size_t)r0 * 64 + c);
            qf[1][kk][1] = *(const unsigned*)(Ql + (size_t)(r0 + 8) * 64 + c);
            qf[1][kk][2] = *(const unsigned*)(Ql + (size_t)r0 * 64 + c + 8);
            qf[1][kk][3] = *(const unsigned*)(Ql + (size_t)(r0 + 8) * 64 + c + 8);
        }
    }

    float oacc[8][4];
#pragma unroll
    for (int t = 0; t < 8; t++) { oacc[t][0] = 0.f; oacc[t][1] = 0.f; oacc[t][2] = 0.f; oacc[t][3] = 0.f; }
    float m0 = -1e30f, m1 = -1e30f, l0 = 0.f, l1 = 0.f;

    att_load_tile(smb, gbase, 0, 0, tid); cp_commit();

    for (int j = 0; j < 32; j++) {
        cp_wait<0>();            // tile j resident
        __syncthreads();         // all warps done reading the stage we overwrite next
        if (j < 31) {
            att_load_tile(smb, gbase, j + 1, (j + 1) & 1, tid);
            cp_commit();         // overlaps with compute of tile j
        }

        unsigned kbase = smb + (unsigned)((j & 1) * ATT_STAGE * 2);
        unsigned vbase = kbase + (unsigned)(2 * ATT_TILE * 2);

        float sacc[8][4];
#pragma unroll
        for (int t = 0; t < 8; t++) { sacc[t][0] = 0.f; sacc[t][1] = 0.f; sacc[t][2] = 0.f; sacc[t][3] = 0.f; }
#pragma unroll
        for (int kk = 0; kk < 4; kk++) {
#pragma unroll
            for (int p = 0; p < 4; p++) {
                int row = p * 16 + ((lane >> 4) << 3) + (lane & 7);
                int col = kk * 16 + ((lane >> 3) & 1) * 8;
                unsigned addr = kbase + (unsigned)((row * ATT_LD + col) * 2);
                unsigned kh0, kh1, kh2, kh3, kl0, kl1, kl2, kl3;
                ldsm_x4(kh0, kh1, kh2, kh3, addr);
                ldsm_x4(kl0, kl1, kl2, kl3, addr + (unsigned)(ATT_TILE * 2));
                mma_fp16(sacc[2 * p],     qf[0][kk], kh0, kh1);
                mma_fp16(sacc[2 * p],     qf[1][kk], kh0, kh1);
                mma_fp16(sacc[2 * p],     qf[0][kk], kl0, kl1);
                mma_fp16(sacc[2 * p + 1], qf[0][kk], kh2, kh3);
                mma_fp16(sacc[2 * p + 1], qf[1][kk], kh2, kh3);
                mma_fp16(sacc[2 * p + 1], qf[0][kk], kl2, kl3);
            }
        }

        float mx0 = -1e30f, mx1 = -1e30f;
#pragma unroll
        for (int t = 0; t < 8; t++) {
            mx0 = fmaxf(mx0, fmaxf(sacc[t][0], sacc[t][1]));
            mx1 = fmaxf(mx1, fmaxf(sacc[t][2], sacc[t][3]));
        }
        mx0 = fmaxf(mx0, __shfl_xor_sync(0xffffffffu, mx0, 1));
        mx0 = fmaxf(mx0, __shfl_xor_sync(0xffffffffu, mx0, 2));
        mx1 = fmaxf(mx1, __shfl_xor_sync(0xffffffffu, mx1, 1));
        mx1 = fmaxf(mx1, __shfl_xor_sync(0xffffffffu, mx1, 2));
        float mn0 = fmaxf(m0, mx0), mn1 = fmaxf(m1, mx1);
        float c0 = __expf(m0 - mn0), c1 = __expf(m1 - mn1);
        m0 = mn0; m1 = mn1;

        float ls0 = 0.f, ls1 = 0.f;
        unsigned pf[2][4][4];
#pragma unroll
        for (int p = 0; p < 4; p++) {
#pragma unroll
            for (int u = 0; u < 2; u++) {
                int t = 2 * p + u;
                float e0 = __expf(sacc[t][0] - mn0);
                float e1 = __expf(sacc[t][1] - mn0);
                float e2 = __expf(sacc[t][2] - mn1);
                float e3 = __expf(sacc[t][3] - mn1);
                ls0 += e0 + e1; ls1 += e2 + e3;
                __half h0 = __float2half_rn(e0), h1 = __float2half_rn(e1);
                __half h2 = __float2half_rn(e2), h3 = __float2half_rn(e3);
                pf[0][p][2 * u]     = pack2(h0, h1);
                pf[0][p][2 * u + 1] = pack2(h2, h3);
                pf[1][p][2 * u]     = pack2(__float2half_rn(e0 - __half2float(h0)),
                                            __float2half_rn(e1 - __half2float(h1)));
                pf[1][p][2 * u + 1] = pack2(__float2half_rn(e2 - __half2float(h2)),
                                            __float2half_rn(e3 - __half2float(h3)));
            }
        }
        ls0 += __shfl_xor_sync(0xffffffffu, ls0, 1);
        ls0 += __shfl_xor_sync(0xffffffffu, ls0, 2);
        ls1 += __shfl_xor_sync(0xffffffffu, ls1, 1);
        ls1 += __shfl_xor_sync(0xffffffffu, ls1, 2);
        l0 = l0 * c0 + ls0;
        l1 = l1 * c1 + ls1;
#pragma unroll
        for (int t = 0; t < 8; t++) { oacc[t][0] *= c0; oacc[t][1] *= c0; oacc[t][2] *= c1; oacc[t][3] *= c1; }

#pragma unroll
        for (int kk = 0; kk < 4; kk++) {
#pragma unroll
            for (int t2 = 0; t2 < 4; t2++) {
                int row = kk * 16 + ((lane >> 3) & 1) * 8 + (lane & 7);
                int col = t2 * 16 + ((lane >> 4) << 3);
                unsigned addr = vbase + (unsigned)((row * ATT_LD + col) * 2);
                unsigned vh0, vh1, vh2, vh3, vl0, vl1, vl2, vl3;
                ldsm_x4t(vh0, vh1, vh2, vh3, addr);
                ldsm_x4t(vl0, vl1, vl2, vl3, addr + (unsigned)(ATT_TILE * 2));
                mma_fp16(oacc[2 * t2],     pf[0][kk], vh0, vh1);
                mma_fp16(oacc[2 * t2],     pf[1][kk], vh0, vh1);
                mma_fp16(oacc[2 * t2],     pf[0][kk], vl0, vl1);
                mma_fp16(oacc[2 * t2 + 1], pf[0][kk], vh2, vh3);
                mma_fp16(oacc[2 * t2 + 1], pf[1][kk], vh2, vh3);
                mma_fp16(oacc[2 * t2 + 1], pf[0][kk], vl2, vl3);
            }
        }
    }

    float i0 = 1.0f / l0, i1 = 1.0f / l1;
    int b = bh >> 4, h = bh & 15;
    int r = q0 + (lane >> 2);
    size_t ob0 = (size_t)(b * 2048 + r) * 1024 + h * 64;
    size_t ob1 = ob0 + (size_t)8 * 1024;
#pragma unroll
    for (int t = 0; t < 8; t++) {
        int c = t * 8 + (lane & 3) * 2;
        float v0 = oacc[t][0] * i0, v1 = oacc[t][1] * i0;
        float v2 = oacc[t][2] * i1, v3 = oacc[t][3] * i1;
        __half h0 = __float2half_rn(v0), h1 = __float2half_rn(v1);
        __half h2 = __float2half_rn(v2), h3 = __float2half_rn(v3);
        *(unsigned*)(g_aoh + ob0 + c) = pack2(h0, h1);
        *(unsigned*)(g_aoh + ob1 + c) = pack2(h2, h3);
        *(unsigned*)(g_aol + ob0 + c) = pack2(__float2half_rn(v0 - __half2float(h0)),
                                              __float2half_rn(v1 - __half2float(h1)));
        *(unsigned*)(g_aol + ob1 + c) = pack2(__float2half_rn(v2 - __half2float(h2)),
                                              __float2half_rn(v3 - __half2float(h3)));
    }
}

// ---------------- host launcher ----------------
extern "C" void kernel_launch(void* const* d_in, const int* in_sizes, int n_in,
                              void* d_out, int out_size) {
    (void)in_sizes; (void)n_in; (void)out_size;
    const float* x    = (const float*)d_in[0];
    const float* Wqkv = (const float*)d_in[1];
    const float* bqkv = (const float*)d_in[2];
    const float* qn_w = (const float*)d_in[3];
    const float* kn_w = (const float*)d_in[4];
    const float* Wout = (const float*)d_in[5];
    const float* bout = (const float*)d_in[6];
    float* out = (float*)d_out;

    // [0] split x + fused RoPE table
    k_split_x<<<(MROWS * D_ / 4) / 256, 256>>>(x, MROWS * D_ / 4);
    // [1] split Wqkv
    k_split_w<<<(D_ * N3D / 4) / 256, 256>>>(Wqkv, 1, D_ * N3D / 4);

    // [2] QKV projection + fused bias/rmsnorm/rope/split epilogue
    cudaFuncSetAttribute(k_gemm, cudaFuncAttributeMaxDynamicSharedMemorySize, GEMM_SMEM);
    k_gemm<<<dim3(N3D / 128, MROWS / 256), 512, GEMM_SMEM>>>(0, bqkv, qn_w, kn_w, nullptr,
                                                             MROWS, N3D, D_);

    // [3] attention (ncu capture index) — 2-stage, 2 CTAs/SM
    cudaFuncSetAttribute(k_attn, cudaFuncAttributeMaxDynamicSharedMemorySize, ATT_SMEM);
    k_attn<<<dim3(L_ / 128, B_ * H_), 256, ATT_SMEM>>>();

    // [4] split Wout (independent of attention; overlaps its tail)
    k_split_w<<<(D_ * D_ / 4) / 256, 256>>>(Wout, 2, D_ * D_ / 4);

    // [5] output projection + bias -> d_out
    k_gemm<<<dim3(D_ / 128, MROWS / 256), 512, GEMM_SMEM>>>(1, bout, qn_w, kn_w, out,
                                                            MROWS, D_, D_);
}

// round 10
// speedup vs baseline: 1.1214x; 1.1214x over previous
#include <cuda_runtime.h>
#include <cuda_fp16.h>

// Problem constants
#define B_ 4
#define L_ 2048
#define D_ 1024
#define H_ 16
#define HD_ 64
#define MROWS 8192      // B*L
#define N3D 3072        // 3*D

// ---------------- device scratch (static allocation only) ----------------
__device__ __align__(16) __half g_xh[MROWS * D_];
__device__ __align__(16) __half g_xl[MROWS * D_];
__device__ __align__(16) __half g_wqh[D_ * N3D];   // [K][N] layout
__device__ __align__(16) __half g_wql[D_ * N3D];
__device__ __align__(16) __half g_woh[D_ * D_];
__device__ __align__(16) __half g_wol[D_ * D_];
__device__ __align__(16) __half g_q_hi[64 * 2048 * 64];
__device__ __align__(16) __half g_q_lo[64 * 2048 * 64];
__device__ __align__(16) __half g_k_hi[64 * 2048 * 64];
__device__ __align__(16) __half g_k_lo[64 * 2048 * 64];
__device__ __align__(16) __half g_v_hi[64 * 2048 * 64];
__device__ __align__(16) __half g_v_lo[64 * 2048 * 64];
__device__ __align__(16) __half g_aoh[MROWS * D_];
__device__ __align__(16) __half g_aol[MROWS * D_];
__device__ __align__(16) float  g_cos[L_ * 32];
__device__ __align__(16) float  g_sin[L_ * 32];

// ---------------- PTX helpers ----------------
__device__ __forceinline__ void mma_fp16(float* d, const unsigned* a, unsigned b0, unsigned b1) {
    asm volatile(
        "mma.sync.aligned.m16n8k16.row.col.f32.f16.f16.f32 "
        "{%0,%1,%2,%3}, {%4,%5,%6,%7}, {%8,%9}, {%0,%1,%2,%3};\n"
        : "+f"(d[0]), "+f"(d[1]), "+f"(d[2]), "+f"(d[3])
        : "r"(a[0]), "r"(a[1]), "r"(a[2]), "r"(a[3]), "r"(b0), "r"(b1));
}
__device__ __forceinline__ void ldsm_x4(unsigned& r0, unsigned& r1, unsigned& r2, unsigned& r3, unsigned a) {
    asm volatile("ldmatrix.sync.aligned.m8n8.x4.shared.b16 {%0,%1,%2,%3}, [%4];\n"
                 : "=r"(r0), "=r"(r1), "=r"(r2), "=r"(r3) : "r"(a));
}
__device__ __forceinline__ void ldsm_x4t(unsigned& r0, unsigned& r1, unsigned& r2, unsigned& r3, unsigned a) {
    asm volatile("ldmatrix.sync.aligned.m8n8.x4.trans.shared.b16 {%0,%1,%2,%3}, [%4];\n"
                 : "=r"(r0), "=r"(r1), "=r"(r2), "=r"(r3) : "r"(a));
}
__device__ __forceinline__ void cp_async16(unsigned dst, const void* src) {
    asm volatile("cp.async.cg.shared.global [%0], [%1], 16;\n" :: "r"(dst), "l"(src));
}
__device__ __forceinline__ void cp_commit() { asm volatile("cp.async.commit_group;\n" ::: "memory"); }
template<int N> __device__ __forceinline__ void cp_wait() {
    asm volatile("cp.async.wait_group %0;\n" :: "n"(N) : "memory");
}
__device__ __forceinline__ unsigned pack2(__half a, __half b) {
    __half2 h = __halves2half2(a, b);
    return *reinterpret_cast<unsigned*>(&h);
}

// ---------------- x split (fp32 -> hi/lo halves) + fused RoPE table ----------------
__global__ void k_split_x(const float* __restrict__ src, int n4) {
    int i = blockIdx.x * blockDim.x + threadIdx.x;
    if (blockIdx.x < 256) {
        int idx = blockIdx.x * 256 + threadIdx.x;   // < 65536 = L_*32
        int l = idx >> 5, f = idx & 31;
        double invd = pow(10000.0, -(double)(2 * f) / 64.0);
        float invf = (float)invd;        // fp32 inv_freq matches jax value
        float ang = (float)l * invf;     // fp32 angle matches reference rounding
        double da = (double)ang;
        g_cos[idx] = (float)cos(da);
        g_sin[idx] = (float)sin(da);
    }
    if (i >= n4) return;
    float4 v = reinterpret_cast<const float4*>(src)[i];
    __half h0 = __float2half(v.x), h1 = __float2half(v.y);
    __half h2 = __float2half(v.z), h3 = __float2half(v.w);
    __half l0 = __float2half(v.x - __half2float(h0));
    __half l1 = __float2half(v.y - __half2float(h1));
    __half l2 = __float2half(v.z - __half2float(h2));
    __half l3 = __float2half(v.w - __half2float(h3));
    reinterpret_cast<__half2*>(g_xh)[2 * i]     = __halves2half2(h0, h1);
    reinterpret_cast<__half2*>(g_xh)[2 * i + 1] = __halves2half2(h2, h3);
    reinterpret_cast<__half2*>(g_xl)[2 * i]     = __halves2half2(l0, l1);
    reinterpret_cast<__half2*>(g_xl)[2 * i + 1] = __halves2half2(l2, l3);
}

// ---------------- weight split (keeps [K][N] layout) ----------------
__global__ void k_split_w(const float* __restrict__ src, int which, int n4) {
    __half* hi = (which == 1) ? g_wqh : g_woh;
    __half* lo = (which == 1) ? g_wql : g_wol;
    int i = blockIdx.x * blockDim.x + threadIdx.x;
    if (i >= n4) return;
    float4 v = reinterpret_cast<const float4*>(src)[i];
    __half h0 = __float2half(v.x), h1 = __float2half(v.y);
    __half h2 = __float2half(v.z), h3 = __float2half(v.w);
    __half l0 = __float2half(v.x - __half2float(h0));
    __half l1 = __float2half(v.y - __half2float(h1));
    __half l2 = __float2half(v.z - __half2float(h2));
    __half l3 = __float2half(v.w - __half2float(h3));
    reinterpret_cast<__half2*>(hi)[2 * i]     = __halves2half2(h0, h1);
    reinterpret_cast<__half2*>(hi)[2 * i + 1] = __halves2half2(h2, h3);
    reinterpret_cast<__half2*>(lo)[2 * i]     = __halves2half2(l0, l1);
    reinterpret_cast<__half2*>(lo)[2 * i + 1] = __halves2half2(l2, l3);
}

// ---------------- split-fp16 raw-mma GEMM, 512 threads, 256x128 tile, 3-stage ----------------
// WHICH==0: A=x(split), B=Wqkv(split), 3-term; fused epilogue: bias+rmsnorm+rope+split
// WHICH==1: A=attn_out(split), B=Wout(hi only), 2-term; epilogue: bias -> Cext fp32
#define GA_LD 40
#define GB_LD 136
#define G_AL (256 * GA_LD)              // 10240 halfs
#define G_BH (2 * 256 * GA_LD)          // 20480
#define G_BLo (G_BH + 32 * GB_LD)       // 24832
#define G_STAGE (G_BH + 2 * 32 * GB_LD) // 29184 halfs per stage
#define GEMM_SMEM (3 * G_STAGE * 2)     // 175104 bytes (epilogue staging reuses this)

template<int WHICH>
__device__ __forceinline__ void gemm_load_stage(unsigned smb, int s,
        const __half* Ah, const __half* Al, const __half* Bh, const __half* Bl,
        int m0, int n0, int k0, int N, int K, int tid) {
    unsigned sb = smb + (unsigned)(s * (G_STAGE * 2));
#pragma unroll
    for (int t = 0; t < 2; t++) {
        int c = tid + t * 512;              // 0..1023 chunks of A per array
        int ar = c >> 2, ac = (c & 3) * 8;
        unsigned da = sb + (unsigned)((ar * GA_LD + ac) * 2);
        cp_async16(da, Ah + (size_t)(m0 + ar) * K + k0 + ac);
        cp_async16(da + (unsigned)(G_AL * 2), Al + (size_t)(m0 + ar) * K + k0 + ac);
    }
    {
        int br = tid >> 4, bc = (tid & 15) * 8;   // 512 chunks of B per array
        unsigned db = sb + (unsigned)((G_BH + br * GB_LD + bc) * 2);
        cp_async16(db, Bh + (size_t)(k0 + br) * N + n0 + bc);
        if (WHICH == 0)
            cp_async16(db + (unsigned)((G_BLo - G_BH) * 2), Bl + (size_t)(k0 + br) * N + n0 + bc);
    }
}

template<int WHICH>
__global__ __launch_bounds__(512, 1) void k_gemm(const float* __restrict__ bias,
                                                 const float* __restrict__ qn_w,
                                                 const float* __restrict__ kn_w,
                                                 float* __restrict__ Cext,
                                                 int M, int N, int K) {
    extern __shared__ __align__(128) char sm_[];
    unsigned smb = (unsigned)__cvta_generic_to_shared(sm_);

    const __half* Ah = WHICH ? g_aoh : g_xh;
    const __half* Al = WHICH ? g_aol : g_xl;
    const __half* Bh = WHICH ? g_woh : g_wqh;
    const __half* Bl = WHICH ? g_wol : g_wql;

    int tid = threadIdx.x;
    int m0 = blockIdx.y * 256, n0 = blockIdx.x * 128;
    int wid = tid >> 5, lane = tid & 31;
    int wm = wid & 7, wn = wid >> 3;   // 8x2 warp grid; warp tile 32 rows x 64 cols

    float acc[2][8][4];                // [m16-tile][n8-tile][c-frag]
#pragma unroll
    for (int mi = 0; mi < 2; mi++)
#pragma unroll
        for (int g = 0; g < 8; g++)
#pragma unroll
            for (int r = 0; r < 4; r++) acc[mi][g][r] = 0.0f;

    gemm_load_stage<WHICH>(smb, 0, Ah, Al, Bh, Bl, m0, n0, 0,  N, K, tid); cp_commit();
    gemm_load_stage<WHICH>(smb, 1, Ah, Al, Bh, Bl, m0, n0, 32, N, K, tid); cp_commit();

    // ldmatrix lane addressing (constant per thread)
    int a_rofs = ((lane >> 3) & 1) * 8 + (lane & 7);   // row-within-16 provider
    int a_cofs = (lane >> 4) * 8;                      // k offset provider
    int b_rofs = ((lane >> 3) & 1) * 8 + (lane & 7);
    int b_cofs = ((lane >> 4) << 3);

    int niter = K / 32;
    for (int it = 0; it < niter; it++) {
        if (it < niter - 1) cp_wait<1>(); else cp_wait<0>();
        __syncthreads();
        int s = it - (it / 3) * 3;
        unsigned sb = smb + (unsigned)(s * (G_STAGE * 2));

#pragma unroll
        for (int kk = 0; kk < 32; kk += 16) {
            // A fragments: 2 m16-tiles, hi & lo
            unsigned ah[2][4], al[2][4];
#pragma unroll
            for (int mi = 0; mi < 2; mi++) {
                unsigned aaddr = sb + (unsigned)(((wm * 32 + mi * 16 + a_rofs) * GA_LD
                                                 + kk + a_cofs) * 2);
                ldsm_x4(ah[mi][0], ah[mi][1], ah[mi][2], ah[mi][3], aaddr);
                ldsm_x4(al[mi][0], al[mi][1], al[mi][2], al[mi][3],
                        aaddr + (unsigned)(G_AL * 2));
            }
            // B: 4 groups of n16, trans-ldmatrix from [k][n]
#pragma unroll
            for (int g = 0; g < 4; g++) {
                unsigned baddr = sb + (unsigned)((G_BH + (kk + b_rofs) * GB_LD
                                                  + wn * 64 + g * 16 + b_cofs) * 2);
                unsigned bh0, bh1, bh2, bh3;
                ldsm_x4t(bh0, bh1, bh2, bh3, baddr);
                unsigned bl0 = 0, bl1 = 0, bl2 = 0, bl3 = 0;
                if (WHICH == 0)
                    ldsm_x4t(bl0, bl1, bl2, bl3, baddr + (unsigned)((G_BLo - G_BH) * 2));
#pragma unroll
                for (int mi = 0; mi < 2; mi++) {
                    mma_fp16(acc[mi][2 * g],     ah[mi], bh0, bh1);
                    mma_fp16(acc[mi][2 * g],     al[mi], bh0, bh1);
                    if (WHICH == 0) mma_fp16(acc[mi][2 * g], ah[mi], bl0, bl1);
                    mma_fp16(acc[mi][2 * g + 1], ah[mi], bh2, bh3);
                    mma_fp16(acc[mi][2 * g + 1], al[mi], bh2, bh3);
                    if (WHICH == 0) mma_fp16(acc[mi][2 * g + 1], ah[mi], bl2, bl3);
                }
            }
        }
        if (it + 2 < niter) {
            int s2 = (it + 2) - ((it + 2) / 3) * 3;
            gemm_load_stage<WHICH>(smb, s2, Ah, Al, Bh, Bl, m0, n0, (it + 2) * 32, N, K, tid);
            cp_commit();
        }
    }

    // ---- epilogue: stage warp tile (32x64) to smem, one lane per row ----
    __syncthreads();                       // pipeline smem free for staging
    float* st = (float*)sm_ + (size_t)wid * (32 * 68);
    {
        int cr = lane >> 2, cc = (lane & 3) * 2;
#pragma unroll
        for (int mi = 0; mi < 2; mi++)
#pragma unroll
            for (int g = 0; g < 8; g++) {
                st[(mi * 16 + cr) * 68 + g * 8 + cc]     = acc[mi][g][0];
                st[(mi * 16 + cr) * 68 + g * 8 + cc + 1] = acc[mi][g][1];
                st[(mi * 16 + cr + 8) * 68 + g * 8 + cc]     = acc[mi][g][2];
                st[(mi * 16 + cr + 8) * 68 + g * 8 + cc + 1] = acc[mi][g][3];
            }
    }
    __syncwarp();

    int gr = m0 + wm * 32 + lane;          // global row (lane owns one row)
    int gn0 = n0 + wn * 64;                // global col base (64-aligned => single head/matrix)
    float* rp = st + lane * 68;

    if (WHICH == 0) {
        int sel = gn0 >> 10;               // 0=Q, 1=K, 2=V
        int h = (gn0 & 1023) >> 6;
        int b = gr >> 11, l = gr & 2047;
        size_t dst = ((size_t)(b * 16 + h) * 2048 + l) * 64;
        __half *hi, *lo;
        if (sel == 0)      { hi = g_q_hi; lo = g_q_lo; }
        else if (sel == 1) { hi = g_k_hi; lo = g_k_lo; }
        else               { hi = g_v_hi; lo = g_v_lo; }

        if (sel == 2) {
#pragma unroll
            for (int c = 0; c < 64; c += 2) {
                float v0 = rp[c]     + bias[gn0 + c];
                float v1 = rp[c + 1] + bias[gn0 + c + 1];
                __half a0 = __float2half(v0), a1 = __float2half(v1);
                *(unsigned*)(hi + dst + c) = pack2(a0, a1);
                *(unsigned*)(lo + dst + c) = pack2(__float2half(v0 - __half2float(a0)),
                                                   __float2half(v1 - __half2float(a1)));
            }
        } else {
            const float* w = (sel == 0) ? qn_w : kn_w;
            float ss = 0.f;
#pragma unroll
            for (int c = 0; c < 64; c++) {
                float v = rp[c] + bias[gn0 + c];
                rp[c] = v;
                ss += v * v;
            }
            float rms = rsqrtf(ss * (1.0f / 64.0f) + 1e-6f);
            float qs = (sel == 0) ? 0.125f : 1.0f;   // fold attn scale into Q
#pragma unroll
            for (int c = 0; c < 32; c += 2) {
                float cv0 = g_cos[l * 32 + c],     sv0 = g_sin[l * 32 + c];
                float cv1 = g_cos[l * 32 + c + 1], sv1 = g_sin[l * 32 + c + 1];
                float t10 = rp[c]      * rms * w[c];
                float t11 = rp[c + 1]  * rms * w[c + 1];
                float t20 = rp[c + 32] * rms * w[c + 32];
                float t21 = rp[c + 33] * rms * w[c + 33];
                float o10 = (t10 * cv0 - t20 * sv0) * qs;
                float o11 = (t11 * cv1 - t21 * sv1) * qs;
                float o20 = (t10 * sv0 + t20 * cv0) * qs;
                float o21 = (t11 * sv1 + t21 * cv1) * qs;
                __half a0 = __float2half(o10), a1 = __float2half(o11);
                __half b0 = __float2half(o20), b1 = __float2half(o21);
                *(unsigned*)(hi + dst + c)      = pack2(a0, a1);
                *(unsigned*)(hi + dst + 32 + c) = pack2(b0, b1);
                *(unsigned*)(lo + dst + c)      = pack2(__float2half(o10 - __half2float(a0)),
                                                        __float2half(o11 - __half2float(a1)));
                *(unsigned*)(lo + dst + 32 + c) = pack2(__float2half(o20 - __half2float(b0)),
                                                        __float2half(o21 - __half2float(b1)));
            }
        }
    } else {
        float* dst = Cext + (size_t)gr * N + gn0;
#pragma unroll
        for (int c = 0; c < 64; c += 4) {
            float4 v;
            v.x = rp[c]     + bias[gn0 + c];
            v.y = rp[c + 1] + bias[gn0 + c + 1];
            v.z = rp[c + 2] + bias[gn0 + c + 2];
            v.w = rp[c + 3] + bias[gn0 + c + 3];
            *reinterpret_cast<float4*>(dst + c) = v;
        }
    }
}

// ---------------- FA2-style flash attention, register-resident, 3-stage cp.async ----------------
// S = QK^T full 3-term split; PV = Ph*Vh + Ph*Vl (P-lo term dropped: +~2.8e-4 RMS, within budget)
#define ATT_LD 72
#define ATT_TILE (64 * ATT_LD)
#define ATT_STAGE (4 * ATT_TILE)
#define ATT_SMEM (3 * ATT_STAGE * 2)

__device__ __forceinline__ void att_load_tile(unsigned smb, size_t gbase, int j, int s, int tid) {
    const __half* src0 = g_k_hi + gbase;
    const __half* src1 = g_k_lo + gbase;
    const __half* src2 = g_v_hi + gbase;
    const __half* src3 = g_v_lo + gbase;
#pragma unroll
    for (int t = 0; t < 2; t++) {
        int c = tid + t * 256;
        int row = c >> 3, col = (c & 7) * 8;
        size_t goff = (size_t)(j * 64 + row) * 64 + col;
        unsigned d = smb + (unsigned)((s * ATT_STAGE + row * ATT_LD + col) * 2);
        cp_async16(d,                                src0 + goff);
        cp_async16(d + (unsigned)(ATT_TILE * 2),     src1 + goff);
        cp_async16(d + (unsigned)(2 * ATT_TILE * 2), src2 + goff);
        cp_async16(d + (unsigned)(3 * ATT_TILE * 2), src3 + goff);
    }
}

__global__ __launch_bounds__(256, 1) void k_attn() {
    extern __shared__ __align__(128) char sm_[];
    unsigned smb = (unsigned)__cvta_generic_to_shared(sm_);

    int tid = threadIdx.x, lane = tid & 31, wid = tid >> 5;
    int bh = blockIdx.y;
    size_t gbase = (size_t)bh * (2048 * 64);
    int q0 = blockIdx.x * 128 + wid * 16;

    unsigned qf[2][4][4];
    {
        const __half* Qh = g_q_hi + gbase;
        const __half* Ql = g_q_lo + gbase;
        int r0 = q0 + (lane >> 2);
        int cb = (lane & 3) * 2;
#pragma unroll
        for (int kk = 0; kk < 4; kk++) {
            int c = kk * 16 + cb;
            qf[0][kk][0] = *(const unsigned*)(Qh + (size_t)r0 * 64 + c);
            qf[0][kk][1] = *(const unsigned*)(Qh + (size_t)(r0 + 8) * 64 + c);
            qf[0][kk][2] = *(const unsigned*)(Qh + (size_t)r0 * 64 + c + 8);
            qf[0][kk][3] = *(const unsigned*)(Qh + (size_t)(r0 + 8) * 64 + c + 8);
            qf[1][kk][0] = *(const unsigned*)(Ql + (size_t)r0 * 64 + c);
            qf[1][kk][1] = *(const unsigned*)(Ql + (size_t)(r0 + 8) * 64 + c);
            qf[1][kk][2] = *(const unsigned*)(Ql + (size_t)r0 * 64 + c + 8);
            qf[1][kk][3] = *(const unsigned*)(Ql + (size_t)(r0 + 8) * 64 + c + 8);
        }
    }

    float oacc[8][4];
#pragma unroll
    for (int t = 0; t < 8; t++) { oacc[t][0] = 0.f; oacc[t][1] = 0.f; oacc[t][2] = 0.f; oacc[t][3] = 0.f; }
    float m0 = -1e30f, m1 = -1e30f, l0 = 0.f, l1 = 0.f;

    att_load_tile(smb, gbase, 0, 0, tid); cp_commit();
    att_load_tile(smb, gbase, 1, 1, tid); cp_commit();

    for (int j = 0; j < 32; j++) {
        int s = j - (j / 3) * 3;
        if (j < 31) cp_wait<1>(); else cp_wait<0>();
        __syncthreads();

        unsigned kbase = smb + (unsigned)(s * ATT_STAGE * 2);
        unsigned vbase = kbase + (unsigned)(2 * ATT_TILE * 2);

        float sacc[8][4];
#pragma unroll
        for (int t = 0; t < 8; t++) { sacc[t][0] = 0.f; sacc[t][1] = 0.f; sacc[t][2] = 0.f; sacc[t][3] = 0.f; }
#pragma unroll
        for (int kk = 0; kk < 4; kk++) {
#pragma unroll
            for (int p = 0; p < 4; p++) {
                int row = p * 16 + ((lane >> 4) << 3) + (lane & 7);
                int col = kk * 16 + ((lane >> 3) & 1) * 8;
                unsigned addr = kbase + (unsigned)((row * ATT_LD + col) * 2);
                unsigned kh0, kh1, kh2, kh3, kl0, kl1, kl2, kl3;
                ldsm_x4(kh0, kh1, kh2, kh3, addr);
                ldsm_x4(kl0, kl1, kl2, kl3, addr + (unsigned)(ATT_TILE * 2));
                mma_fp16(sacc[2 * p],     qf[0][kk], kh0, kh1);
                mma_fp16(sacc[2 * p],     qf[1][kk], kh0, kh1);
                mma_fp16(sacc[2 * p],     qf[0][kk], kl0, kl1);
                mma_fp16(sacc[2 * p + 1], qf[0][kk], kh2, kh3);
                mma_fp16(sacc[2 * p + 1], qf[1][kk], kh2, kh3);
                mma_fp16(sacc[2 * p + 1], qf[0][kk], kl2, kl3);
            }
        }

        float mx0 = -1e30f, mx1 = -1e30f;
#pragma unroll
        for (int t = 0; t < 8; t++) {
            mx0 = fmaxf(mx0, fmaxf(sacc[t][0], sacc[t][1]));
            mx1 = fmaxf(mx1, fmaxf(sacc[t][2], sacc[t][3]));
        }
        mx0 = fmaxf(mx0, __shfl_xor_sync(0xffffffffu, mx0, 1));
        mx0 = fmaxf(mx0, __shfl_xor_sync(0xffffffffu, mx0, 2));
        mx1 = fmaxf(mx1, __shfl_xor_sync(0xffffffffu, mx1, 1));
        mx1 = fmaxf(mx1, __shfl_xor_sync(0xffffffffu, mx1, 2));
        float mn0 = fmaxf(m0, mx0), mn1 = fmaxf(m1, mx1);
        float c0 = __expf(m0 - mn0), c1 = __expf(m1 - mn1);
        m0 = mn0; m1 = mn1;

        float ls0 = 0.f, ls1 = 0.f;
        unsigned pf[4][4];   // P hi only (lo term dropped)
#pragma unroll
        for (int p = 0; p < 4; p++) {
#pragma unroll
            for (int u = 0; u < 2; u++) {
                int t = 2 * p + u;
                float e0 = __expf(sacc[t][0] - mn0);
                float e1 = __expf(sacc[t][1] - mn0);
                float e2 = __expf(sacc[t][2] - mn1);
                float e3 = __expf(sacc[t][3] - mn1);
                ls0 += e0 + e1; ls1 += e2 + e3;
                pf[p][2 * u]     = pack2(__float2half_rn(e0), __float2half_rn(e1));
                pf[p][2 * u + 1] = pack2(__float2half_rn(e2), __float2half_rn(e3));
            }
        }
        ls0 += __shfl_xor_sync(0xffffffffu, ls0, 1);
        ls0 += __shfl_xor_sync(0xffffffffu, ls0, 2);
        ls1 += __shfl_xor_sync(0xffffffffu, ls1, 1);
        ls1 += __shfl_xor_sync(0xffffffffu, ls1, 2);
        l0 = l0 * c0 + ls0;
        l1 = l1 * c1 + ls1;
#pragma unroll
        for (int t = 0; t < 8; t++) { oacc[t][0] *= c0; oacc[t][1] *= c0; oacc[t][2] *= c1; oacc[t][3] *= c1; }

#pragma unroll
        for (int kk = 0; kk < 4; kk++) {
#pragma unroll
            for (int t2 = 0; t2 < 4; t2++) {
                int row = kk * 16 + ((lane >> 3) & 1) * 8 + (lane & 7);
                int col = t2 * 16 + ((lane >> 4) << 3);
                unsigned addr = vbase + (unsigned)((row * ATT_LD + col) * 2);
                unsigned vh0, vh1, vh2, vh3, vl0, vl1, vl2, vl3;
                ldsm_x4t(vh0, vh1, vh2, vh3, addr);
                ldsm_x4t(vl0, vl1, vl2, vl3, addr + (unsigned)(ATT_TILE * 2));
                mma_fp16(oacc[2 * t2],     pf[kk], vh0, vh1);
                mma_fp16(oacc[2 * t2],     pf[kk], vl0, vl1);
                mma_fp16(oacc[2 * t2 + 1], pf[kk], vh2, vh3);
                mma_fp16(oacc[2 * t2 + 1], pf[kk], vl2, vl3);
            }
        }

        if (j + 2 < 32) {
            int s2 = (j + 2) - ((j + 2) / 3) * 3;
            att_load_tile(smb, gbase, j + 2, s2, tid);
            cp_commit();
        }
    }

    float i0 = 1.0f / l0, i1 = 1.0f / l1;
    int b = bh >> 4, h = bh & 15;
    int r = q0 + (lane >> 2);
    size_t ob0 = (size_t)(b * 2048 + r) * 1024 + h * 64;
    size_t ob1 = ob0 + (size_t)8 * 1024;
#pragma unroll
    for (int t = 0; t < 8; t++) {
        int c = t * 8 + (lane & 3) * 2;
        float v0 = oacc[t][0] * i0, v1 = oacc[t][1] * i0;
        float v2 = oacc[t][2] * i1, v3 = oacc[t][3] * i1;
        __half h0 = __float2half_rn(v0), h1 = __float2half_rn(v1);
        __half h2 = __float2half_rn(v2), h3 = __float2half_rn(v3);
        *(unsigned*)(g_aoh + ob0 + c) = pack2(h0, h1);
        *(unsigned*)(g_aoh + ob1 + c) = pack2(h2, h3);
        *(unsigned*)(g_aol + ob0 + c) = pack2(__float2half_rn(v0 - __half2float(h0)),
                                              __float2half_rn(v1 - __half2float(h1)));
        *(unsigned*)(g_aol + ob1 + c) = pack2(__float2half_rn(v2 - __half2float(h2)),
                                              __float2half_rn(v3 - __half2float(h3)));
    }
}

// ---------------- host launcher ----------------
extern "C" void kernel_launch(void* const* d_in, const int* in_sizes, int n_in,
                              void* d_out, int out_size) {
    (void)in_sizes; (void)n_in; (void)out_size;
    const float* x    = (const float*)d_in[0];
    const float* Wqkv = (const float*)d_in[1];
    const float* bqkv = (const float*)d_in[2];
    const float* qn_w = (const float*)d_in[3];
    const float* kn_w = (const float*)d_in[4];
    const float* Wout = (const float*)d_in[5];
    const float* bout = (const float*)d_in[6];
    float* out = (float*)d_out;

    // [0] split x + fused RoPE table
    k_split_x<<<(MROWS * D_ / 4) / 256, 256>>>(x, MROWS * D_ / 4);
    // [1] split Wqkv
    k_split_w<<<(D_ * N3D / 4) / 256, 256>>>(Wqkv, 1, D_ * N3D / 4);

    // [2] QKV projection (3-term) + fused bias/rmsnorm/rope/split epilogue
    cudaFuncSetAttribute(k_gemm<0>, cudaFuncAttributeMaxDynamicSharedMemorySize, GEMM_SMEM);
    k_gemm<0><<<dim3(N3D / 128, MROWS / 256), 512, GEMM_SMEM>>>(bqkv, qn_w, kn_w, nullptr,
                                                                MROWS, N3D, D_);

    // [3] attention (ncu capture index) — 3-stage, PV P-lo dropped
    cudaFuncSetAttribute(k_attn, cudaFuncAttributeMaxDynamicSharedMemorySize, ATT_SMEM);
    k_attn<<<dim3(L_ / 128, B_ * H_), 256, ATT_SMEM>>>();

    // [4] split Wout (independent of attention; overlaps its tail)
    k_split_w<<<(D_ * D_ / 4) / 256, 256>>>(Wout, 2, D_ * D_ / 4);

    // [5] output projection (2-term: Wout-lo dropped) + bias -> d_out
    cudaFuncSetAttribute(k_gemm<1>, cudaFuncAttributeMaxDynamicSharedMemorySize, GEMM_SMEM);
    k_gemm<1><<<dim3(D_ / 128, MROWS / 256), 512, GEMM_SMEM>>>(bout, qn_w, kn_w, out,
                                                               MROWS, D_, D_);
}

// round 13
// speedup vs baseline: 1.2278x; 1.0949x over previous
#include <cuda_runtime.h>
#include <cuda_fp16.h>

// Problem constants
#define B_ 4
#define L_ 2048
#define D_ 1024
#define H_ 16
#define HD_ 64
#define MROWS 8192      // B*L
#define N3D 3072        // 3*D

// ---------------- device scratch (static allocation only) ----------------
__device__ __align__(16) __half g_xh[MROWS * D_];
__device__ __align__(16) __half g_xl[MROWS * D_];
__device__ __align__(16) __half g_wqh[D_ * N3D];   // [K][N] layout
__device__ __align__(16) __half g_wql[D_ * N3D];
__device__ __align__(16) __half g_woh[D_ * D_];
__device__ __align__(16) __half g_wol[D_ * D_];
__device__ __align__(16) __half g_q_hi[64 * 2048 * 64];
__device__ __align__(16) __half g_q_lo[64 * 2048 * 64];
__device__ __align__(16) __half g_k_hi[64 * 2048 * 64];
__device__ __align__(16) __half g_v_hi[64 * 2048 * 64];
__device__ __align__(16) __half g_aoh[MROWS * D_];
__device__ __align__(16) __half g_aol[MROWS * D_];
__device__ __align__(16) float  g_cos[L_ * 32];
__device__ __align__(16) float  g_sin[L_ * 32];

// ---------------- PTX helpers ----------------
__device__ __forceinline__ void mma_fp16(float* d, const unsigned* a, unsigned b0, unsigned b1) {
    asm volatile(
        "mma.sync.aligned.m16n8k16.row.col.f32.f16.f16.f32 "
        "{%0,%1,%2,%3}, {%4,%5,%6,%7}, {%8,%9}, {%0,%1,%2,%3};\n"
        : "+f"(d[0]), "+f"(d[1]), "+f"(d[2]), "+f"(d[3])
        : "r"(a[0]), "r"(a[1]), "r"(a[2]), "r"(a[3]), "r"(b0), "r"(b1));
}
__device__ __forceinline__ void ldsm_x4(unsigned& r0, unsigned& r1, unsigned& r2, unsigned& r3, unsigned a) {
    asm volatile("ldmatrix.sync.aligned.m8n8.x4.shared.b16 {%0,%1,%2,%3}, [%4];\n"
                 : "=r"(r0), "=r"(r1), "=r"(r2), "=r"(r3) : "r"(a));
}
__device__ __forceinline__ void ldsm_x4t(unsigned& r0, unsigned& r1, unsigned& r2, unsigned& r3, unsigned a) {
    asm volatile("ldmatrix.sync.aligned.m8n8.x4.trans.shared.b16 {%0,%1,%2,%3}, [%4];\n"
                 : "=r"(r0), "=r"(r1), "=r"(r2), "=r"(r3) : "r"(a));
}
__device__ __forceinline__ void cp_async16(unsigned dst, const void* src) {
    asm volatile("cp.async.cg.shared.global [%0], [%1], 16;\n" :: "r"(dst), "l"(src));
}
__device__ __forceinline__ void cp_commit() { asm volatile("cp.async.commit_group;\n" ::: "memory"); }
template<int N> __device__ __forceinline__ void cp_wait() {
    asm volatile("cp.async.wait_group %0;\n" :: "n"(N) : "memory");
}
__device__ __forceinline__ unsigned pack2(__half a, __half b) {
    __half2 h = __halves2half2(a, b);
    return *reinterpret_cast<unsigned*>(&h);
}

// ---------------- x split (fp32 -> hi/lo halves) + fused RoPE table ----------------
__global__ void k_split_x(const float* __restrict__ src, int n4) {
    int i = blockIdx.x * blockDim.x + threadIdx.x;
    if (blockIdx.x < 256) {
        int idx = blockIdx.x * 256 + threadIdx.x;   // < 65536 = L_*32
        int l = idx >> 5, f = idx & 31;
        double invd = pow(10000.0, -(double)(2 * f) / 64.0);
        float invf = (float)invd;        // fp32 inv_freq matches jax value
        float ang = (float)l * invf;     // fp32 angle matches reference rounding
        double da = (double)ang;
        g_cos[idx] = (float)cos(da);
        g_sin[idx] = (float)sin(da);
    }
    if (i >= n4) return;
    float4 v = reinterpret_cast<const float4*>(src)[i];
    __half h0 = __float2half(v.x), h1 = __float2half(v.y);
    __half h2 = __float2half(v.z), h3 = __float2half(v.w);
    __half l0 = __float2half(v.x - __half2float(h0));
    __half l1 = __float2half(v.y - __half2float(h1));
    __half l2 = __float2half(v.z - __half2float(h2));
    __half l3 = __float2half(v.w - __half2float(h3));
    reinterpret_cast<__half2*>(g_xh)[2 * i]     = __halves2half2(h0, h1);
    reinterpret_cast<__half2*>(g_xh)[2 * i + 1] = __halves2half2(h2, h3);
    reinterpret_cast<__half2*>(g_xl)[2 * i]     = __halves2half2(l0, l1);
    reinterpret_cast<__half2*>(g_xl)[2 * i + 1] = __halves2half2(l2, l3);
}

// ---------------- weight split (keeps [K][N] layout) ----------------
__global__ void k_split_w(const float* __restrict__ src, int which, int n4) {
    __half* hi = (which == 1) ? g_wqh : g_woh;
    __half* lo = (which == 1) ? g_wql : g_wol;
    int i = blockIdx.x * blockDim.x + threadIdx.x;
    if (i >= n4) return;
    float4 v = reinterpret_cast<const float4*>(src)[i];
    __half h0 = __float2half(v.x), h1 = __float2half(v.y);
    __half h2 = __float2half(v.z), h3 = __float2half(v.w);
    __half l0 = __float2half(v.x - __half2float(h0));
    __half l1 = __float2half(v.y - __half2float(h1));
    __half l2 = __float2half(v.z - __half2float(h2));
    __half l3 = __float2half(v.w - __half2float(h3));
    reinterpret_cast<__half2*>(hi)[2 * i]     = __halves2half2(h0, h1);
    reinterpret_cast<__half2*>(hi)[2 * i + 1] = __halves2half2(h2, h3);
    reinterpret_cast<__half2*>(lo)[2 * i]     = __halves2half2(l0, l1);
    reinterpret_cast<__half2*>(lo)[2 * i + 1] = __halves2half2(l2, l3);
}

// ---------------- split-fp16 raw-mma GEMM, 512 threads, 256x128 tile, 3-stage ----------------
// WHICH==0: A=x(split), B=Wqkv(split), 3-term; fused epilogue: bias+rmsnorm+rope+split
// WHICH==1: A=attn_out(split), B=Wout(hi only), 2-term; epilogue: bias -> Cext fp32
#define GA_LD 40
#define GB_LD 136
#define G_AL (256 * GA_LD)              // 10240 halfs
#define G_BH (2 * 256 * GA_LD)          // 20480
#define G_BLo (G_BH + 32 * GB_LD)       // 24832
#define G_STAGE (G_BH + 2 * 32 * GB_LD) // 29184 halfs per stage
#define GEMM_SMEM (3 * G_STAGE * 2)     // 175104 bytes (epilogue staging reuses this)

template<int WHICH>
__device__ __forceinline__ void gemm_load_stage(unsigned smb, int s,
        const __half* Ah, const __half* Al, const __half* Bh, const __half* Bl,
        int m0, int n0, int k0, int N, int K, int tid) {
    unsigned sb = smb + (unsigned)(s * (G_STAGE * 2));
#pragma unroll
    for (int t = 0; t < 2; t++) {
        int c = tid + t * 512;              // 0..1023 chunks of A per array
        int ar = c >> 2, ac = (c & 3) * 8;
        unsigned da = sb + (unsigned)((ar * GA_LD + ac) * 2);
        cp_async16(da, Ah + (size_t)(m0 + ar) * K + k0 + ac);
        cp_async16(da + (unsigned)(G_AL * 2), Al + (size_t)(m0 + ar) * K + k0 + ac);
    }
    {
        int br = tid >> 4, bc = (tid & 15) * 8;   // 512 chunks of B per array
        unsigned db = sb + (unsigned)((G_BH + br * GB_LD + bc) * 2);
        cp_async16(db, Bh + (size_t)(k0 + br) * N + n0 + bc);
        if (WHICH == 0)
            cp_async16(db + (unsigned)((G_BLo - G_BH) * 2), Bl + (size_t)(k0 + br) * N + n0 + bc);
    }
}

template<int WHICH>
__global__ __launch_bounds__(512, 1) void k_gemm(const float* __restrict__ bias,
                                                 const float* __restrict__ qn_w,
                                                 const float* __restrict__ kn_w,
                                                 float* __restrict__ Cext,
                                                 int M, int N, int K) {
    extern __shared__ __align__(128) char sm_[];
    unsigned smb = (unsigned)__cvta_generic_to_shared(sm_);

    const __half* Ah = WHICH ? g_aoh : g_xh;
    const __half* Al = WHICH ? g_aol : g_xl;
    const __half* Bh = WHICH ? g_woh : g_wqh;
    const __half* Bl = WHICH ? g_wol : g_wql;

    int tid = threadIdx.x;
    int m0 = blockIdx.y * 256, n0 = blockIdx.x * 128;
    int wid = tid >> 5, lane = tid & 31;
    int wm = wid & 7, wn = wid >> 3;   // 8x2 warp grid; warp tile 32 rows x 64 cols

    float acc[2][8][4];                // [m16-tile][n8-tile][c-frag]
#pragma unroll
    for (int mi = 0; mi < 2; mi++)
#pragma unroll
        for (int g = 0; g < 8; g++)
#pragma unroll
            for (int r = 0; r < 4; r++) acc[mi][g][r] = 0.0f;

    gemm_load_stage<WHICH>(smb, 0, Ah, Al, Bh, Bl, m0, n0, 0,  N, K, tid); cp_commit();
    gemm_load_stage<WHICH>(smb, 1, Ah, Al, Bh, Bl, m0, n0, 32, N, K, tid); cp_commit();

    // ldmatrix lane addressing (constant per thread)
    int a_rofs = ((lane >> 3) & 1) * 8 + (lane & 7);   // row-within-16 provider
    int a_cofs = (lane >> 4) * 8;                      // k offset provider
    int b_rofs = ((lane >> 3) & 1) * 8 + (lane & 7);
    int b_cofs = ((lane >> 4) << 3);

    int niter = K / 32;
    for (int it = 0; it < niter; it++) {
        if (it < niter - 1) cp_wait<1>(); else cp_wait<0>();
        __syncthreads();
        int s = it - (it / 3) * 3;
        unsigned sb = smb + (unsigned)(s * (G_STAGE * 2));

#pragma unroll
        for (int kk = 0; kk < 32; kk += 16) {
            // A fragments: 2 m16-tiles, hi & lo
            unsigned ah[2][4], al[2][4];
#pragma unroll
            for (int mi = 0; mi < 2; mi++) {
                unsigned aaddr = sb + (unsigned)(((wm * 32 + mi * 16 + a_rofs) * GA_LD
                                                 + kk + a_cofs) * 2);
                ldsm_x4(ah[mi][0], ah[mi][1], ah[mi][2], ah[mi][3], aaddr);
                ldsm_x4(al[mi][0], al[mi][1], al[mi][2], al[mi][3],
                        aaddr + (unsigned)(G_AL * 2));
            }
            // B: 4 groups of n16, trans-ldmatrix from [k][n]
#pragma unroll
            for (int g = 0; g < 4; g++) {
                unsigned baddr = sb + (unsigned)((G_BH + (kk + b_rofs) * GB_LD
                                                  + wn * 64 + g * 16 + b_cofs) * 2);
                unsigned bh0, bh1, bh2, bh3;
                ldsm_x4t(bh0, bh1, bh2, bh3, baddr);
                unsigned bl0 = 0, bl1 = 0, bl2 = 0, bl3 = 0;
                if (WHICH == 0)
                    ldsm_x4t(bl0, bl1, bl2, bl3, baddr + (unsigned)((G_BLo - G_BH) * 2));
#pragma unroll
                for (int mi = 0; mi < 2; mi++) {
                    mma_fp16(acc[mi][2 * g],     ah[mi], bh0, bh1);
                    mma_fp16(acc[mi][2 * g],     al[mi], bh0, bh1);
                    if (WHICH == 0) mma_fp16(acc[mi][2 * g], ah[mi], bl0, bl1);
                    mma_fp16(acc[mi][2 * g + 1], ah[mi], bh2, bh3);
                    mma_fp16(acc[mi][2 * g + 1], al[mi], bh2, bh3);
                    if (WHICH == 0) mma_fp16(acc[mi][2 * g + 1], ah[mi], bl2, bl3);
                }
            }
        }
        if (it + 2 < niter) {
            int s2 = (it + 2) - ((it + 2) / 3) * 3;
            gemm_load_stage<WHICH>(smb, s2, Ah, Al, Bh, Bl, m0, n0, (it + 2) * 32, N, K, tid);
            cp_commit();
        }
    }

    // ---- epilogue: stage warp tile (32x64) to smem, one lane per row ----
    __syncthreads();                       // pipeline smem free for staging
    float* st = (float*)sm_ + (size_t)wid * (32 * 68);
    {
        int cr = lane >> 2, cc = (lane & 3) * 2;
#pragma unroll
        for (int mi = 0; mi < 2; mi++)
#pragma unroll
            for (int g = 0; g < 8; g++) {
                st[(mi * 16 + cr) * 68 + g * 8 + cc]     = acc[mi][g][0];
                st[(mi * 16 + cr) * 68 + g * 8 + cc + 1] = acc[mi][g][1];
                st[(mi * 16 + cr + 8) * 68 + g * 8 + cc]     = acc[mi][g][2];
                st[(mi * 16 + cr + 8) * 68 + g * 8 + cc + 1] = acc[mi][g][3];
            }
    }
    __syncwarp();

    int gr = m0 + wm * 32 + lane;          // global row (lane owns one row)
    int gn0 = n0 + wn * 64;                // global col base (64-aligned => single head/matrix)
    float* rp = st + lane * 68;

    if (WHICH == 0) {
        int sel = gn0 >> 10;               // 0=Q, 1=K, 2=V
        int h = (gn0 & 1023) >> 6;
        int b = gr >> 11, l = gr & 2047;
        size_t dst = ((size_t)(b * 16 + h) * 2048 + l) * 64;

        if (sel == 2) {
            // V: hi only (V-lo term dropped in PV)
#pragma unroll
            for (int c = 0; c < 64; c += 2) {
                float v0 = rp[c]     + bias[gn0 + c];
                float v1 = rp[c + 1] + bias[gn0 + c + 1];
                *(unsigned*)(g_v_hi + dst + c) = pack2(__float2half(v0), __float2half(v1));
            }
        } else {
            const float* w = (sel == 0) ? qn_w : kn_w;
            float ss = 0.f;
#pragma unroll
            for (int c = 0; c < 64; c++) {
                float v = rp[c] + bias[gn0 + c];
                rp[c] = v;
                ss += v * v;
            }
            float rms = rsqrtf(ss * (1.0f / 64.0f) + 1e-6f);
            float qs = (sel == 0) ? 0.125f : 1.0f;   // fold attn scale into Q
#pragma unroll
            for (int c = 0; c < 32; c += 2) {
                float cv0 = g_cos[l * 32 + c],     sv0 = g_sin[l * 32 + c];
                float cv1 = g_cos[l * 32 + c + 1], sv1 = g_sin[l * 32 + c + 1];
                float t10 = rp[c]      * rms * w[c];
                float t11 = rp[c + 1]  * rms * w[c + 1];
                float t20 = rp[c + 32] * rms * w[c + 32];
                float t21 = rp[c + 33] * rms * w[c + 33];
                float o10 = (t10 * cv0 - t20 * sv0) * qs;
                float o11 = (t11 * cv1 - t21 * sv1) * qs;
                float o20 = (t10 * sv0 + t20 * cv0) * qs;
                float o21 = (t11 * sv1 + t21 * cv1) * qs;
                __half a0 = __float2half(o10), a1 = __float2half(o11);
                __half b0 = __float2half(o20), b1 = __float2half(o21);
                if (sel == 0) {
                    // Q: hi + lo (Q-lo term kept in S)
                    *(unsigned*)(g_q_hi + dst + c)      = pack2(a0, a1);
                    *(unsigned*)(g_q_hi + dst + 32 + c) = pack2(b0, b1);
                    *(unsigned*)(g_q_lo + dst + c)      = pack2(__float2half(o10 - __half2float(a0)),
                                                                __float2half(o11 - __half2float(a1)));
                    *(unsigned*)(g_q_lo + dst + 32 + c) = pack2(__float2half(o20 - __half2float(b0)),
                                                                __float2half(o21 - __half2float(b1)));
                } else {
                    // K: hi only (K-lo term dropped in S)
                    *(unsigned*)(g_k_hi + dst + c)      = pack2(a0, a1);
                    *(unsigned*)(g_k_hi + dst + 32 + c) = pack2(b0, b1);
                }
            }
        }
    } else {
        float* dst = Cext + (size_t)gr * N + gn0;
#pragma unroll
        for (int c = 0; c < 64; c += 4) {
            float4 v;
            v.x = rp[c]     + bias[gn0 + c];
            v.y = rp[c + 1] + bias[gn0 + c + 1];
            v.z = rp[c + 2] + bias[gn0 + c + 2];
            v.w = rp[c + 3] + bias[gn0 + c + 3];
            *reinterpret_cast<float4*>(dst + c) = v;
        }
    }
}

// ---------------- FA2-style flash attention, register-resident, 3-stage cp.async ----------------
// S = Qh*Kh + Ql*Kh (K-lo dropped); PV = Ph*Vh (P-lo, V-lo dropped).
// Kept correction terms: Q-lo (largest residual after 0.125 scale), A-lo & W-lo paths in GEMMs.
#define ATT_LD 72
#define ATT_TILE (64 * ATT_LD)
#define ATT_STAGE (2 * ATT_TILE)        // Kh + Vh only
#define ATT_SMEM (3 * ATT_STAGE * 2)    // 55296 bytes

__device__ __forceinline__ void att_load_tile(unsigned smb, size_t gbase, int j, int s, int tid) {
    const __half* src0 = g_k_hi + gbase;
    const __half* src1 = g_v_hi + gbase;
#pragma unroll
    for (int t = 0; t < 2; t++) {
        int c = tid + t * 256;
        int row = c >> 3, col = (c & 7) * 8;
        size_t goff = (size_t)(j * 64 + row) * 64 + col;
        unsigned d = smb + (unsigned)((s * ATT_STAGE + row * ATT_LD + col) * 2);
        cp_async16(d,                            src0 + goff);
        cp_async16(d + (unsigned)(ATT_TILE * 2), src1 + goff);
    }
}

__global__ __launch_bounds__(256, 1) void k_attn() {
    extern __shared__ __align__(128) char sm_[];
    unsigned smb = (unsigned)__cvta_generic_to_shared(sm_);

    int tid = threadIdx.x, lane = tid & 31, wid = tid >> 5;
    int bh = blockIdx.y;
    size_t gbase = (size_t)bh * (2048 * 64);
    int q0 = blockIdx.x * 128 + wid * 16;

    unsigned qf[2][4][4];
    {
        const __half* Qh = g_q_hi + gbase;
        const __half* Ql = g_q_lo + gbase;
        int r0 = q0 + (lane >> 2);
        int cb = (lane & 3) * 2;
#pragma unroll
        for (int kk = 0; kk < 4; kk++) {
            int c = kk * 16 + cb;
            qf[0][kk][0] = *(const unsigned*)(Qh + (size_t)r0 * 64 + c);
            qf[0][kk][1] = *(const unsigned*)(Qh + (size_t)(r0 + 8) * 64 + c);
            qf[0][kk][2] = *(const unsigned*)(Qh + (size_t)r0 * 64 + c + 8);
            qf[0][kk][3] = *(const unsigned*)(Qh + (size_t)(r0 + 8) * 64 + c + 8);
            qf[1][kk][0] = *(const unsigned*)(Ql + (size_t)r0 * 64 + c);
            qf[1][kk][1] = *(const unsigned*)(Ql + (size_t)(r0 + 8) * 64 + c);
            qf[1][kk][2] = *(const unsigned*)(Ql + (size_t)r0 * 64 + c + 8);
            qf[1][kk][3] = *(const unsigned*)(Ql + (size_t)(r0 + 8) * 64 + c + 8);
        }
    }

    float oacc[8][4];
#pragma unroll
    for (int t = 0; t < 8; t++) { oacc[t][0] = 0.f; oacc[t][1] = 0.f; oacc[t][2] = 0.f; oacc[t][3] = 0.f; }
    float m0 = -1e30f, m1 = -1e30f, l0 = 0.f, l1 = 0.f;

    att_load_tile(smb, gbase, 0, 0, tid); cp_commit();
    att_load_tile(smb, gbase, 1, 1, tid); cp_commit();

    for (int j = 0; j < 32; j++) {
        int s = j - (j / 3) * 3;
        if (j < 31) cp_wait<1>(); else cp_wait<0>();
        __syncthreads();

        unsigned kbase = smb + (unsigned)(s * ATT_STAGE * 2);
        unsigned vbase = kbase + (unsigned)(ATT_TILE * 2);

        float sacc[8][4];
#pragma unroll
        for (int t = 0; t < 8; t++) { sacc[t][0] = 0.f; sacc[t][1] = 0.f; sacc[t][2] = 0.f; sacc[t][3] = 0.f; }
#pragma unroll
        for (int kk = 0; kk < 4; kk++) {
#pragma unroll
            for (int p = 0; p < 4; p++) {
                int row = p * 16 + ((lane >> 4) << 3) + (lane & 7);
                int col = kk * 16 + ((lane >> 3) & 1) * 8;
                unsigned addr = kbase + (unsigned)((row * ATT_LD + col) * 2);
                unsigned kh0, kh1, kh2, kh3;
                ldsm_x4(kh0, kh1, kh2, kh3, addr);
                mma_fp16(sacc[2 * p],     qf[0][kk], kh0, kh1);
                mma_fp16(sacc[2 * p],     qf[1][kk], kh0, kh1);
                mma_fp16(sacc[2 * p + 1], qf[0][kk], kh2, kh3);
                mma_fp16(sacc[2 * p + 1], qf[1][kk], kh2, kh3);
            }
        }

        float mx0 = -1e30f, mx1 = -1e30f;
#pragma unroll
        for (int t = 0; t < 8; t++) {
            mx0 = fmaxf(mx0, fmaxf(sacc[t][0], sacc[t][1]));
            mx1 = fmaxf(mx1, fmaxf(sacc[t][2], sacc[t][3]));
        }
        mx0 = fmaxf(mx0, __shfl_xor_sync(0xffffffffu, mx0, 1));
        mx0 = fmaxf(mx0, __shfl_xor_sync(0xffffffffu, mx0, 2));
        mx1 = fmaxf(mx1, __shfl_xor_sync(0xffffffffu, mx1, 1));
        mx1 = fmaxf(mx1, __shfl_xor_sync(0xffffffffu, mx1, 2));
        float mn0 = fmaxf(m0, mx0), mn1 = fmaxf(m1, mx1);
        float c0 = __expf(m0 - mn0), c1 = __expf(m1 - mn1);
        m0 = mn0; m1 = mn1;

        float ls0 = 0.f, ls1 = 0.f;
        unsigned pf[4][4];   // P hi only
#pragma unroll
        for (int p = 0; p < 4; p++) {
#pragma unroll
            for (int u = 0; u < 2; u++) {
                int t = 2 * p + u;
                float e0 = __expf(sacc[t][0] - mn0);
                float e1 = __expf(sacc[t][1] - mn0);
                float e2 = __expf(sacc[t][2] - mn1);
                float e3 = __expf(sacc[t][3] - mn1);
                ls0 += e0 + e1; ls1 += e2 + e3;
                pf[p][2 * u]     = pack2(__float2half_rn(e0), __float2half_rn(e1));
                pf[p][2 * u + 1] = pack2(__float2half_rn(e2), __float2half_rn(e3));
            }
        }
        ls0 += __shfl_xor_sync(0xffffffffu, ls0, 1);
        ls0 += __shfl_xor_sync(0xffffffffu, ls0, 2);
        ls1 += __shfl_xor_sync(0xffffffffu, ls1, 1);
        ls1 += __shfl_xor_sync(0xffffffffu, ls1, 2);
        l0 = l0 * c0 + ls0;
        l1 = l1 * c1 + ls1;
#pragma unroll
        for (int t = 0; t < 8; t++) { oacc[t][0] *= c0; oacc[t][1] *= c0; oacc[t][2] *= c1; oacc[t][3] *= c1; }

#pragma unroll
        for (int kk = 0; kk < 4; kk++) {
#pragma unroll
            for (int t2 = 0; t2 < 4; t2++) {
                int row = kk * 16 + ((lane >> 3) & 1) * 8 + (lane & 7);
                int col = t2 * 16 + ((lane >> 4) << 3);
                unsigned addr = vbase + (unsigned)((row * ATT_LD + col) * 2);
                unsigned vh0, vh1, vh2, vh3;
                ldsm_x4t(vh0, vh1, vh2, vh3, addr);
                mma_fp16(oacc[2 * t2],     pf[kk], vh0, vh1);
                mma_fp16(oacc[2 * t2 + 1], pf[kk], vh2, vh3);
            }
        }

        if (j + 2 < 32) {
            int s2 = (j + 2) - ((j + 2) / 3) * 3;
            att_load_tile(smb, gbase, j + 2, s2, tid);
            cp_commit();
        }
    }

    float i0 = 1.0f / l0, i1 = 1.0f / l1;
    int b = bh >> 4, h = bh & 15;
    int r = q0 + (lane >> 2);
    size_t ob0 = (size_t)(b * 2048 + r) * 1024 + h * 64;
    size_t ob1 = ob0 + (size_t)8 * 1024;
#pragma unroll
    for (int t = 0; t < 8; t++) {
        int c = t * 8 + (lane & 3) * 2;
        float v0 = oacc[t][0] * i0, v1 = oacc[t][1] * i0;
        float v2 = oacc[t][2] * i1, v3 = oacc[t][3] * i1;
        __half h0 = __float2half_rn(v0), h1 = __float2half_rn(v1);
        __half h2 = __float2half_rn(v2), h3 = __float2half_rn(v3);
        *(unsigned*)(g_aoh + ob0 + c) = pack2(h0, h1);
        *(unsigned*)(g_aoh + ob1 + c) = pack2(h2, h3);
        *(unsigned*)(g_aol + ob0 + c) = pack2(__float2half_rn(v0 - __half2float(h0)),
                                              __float2half_rn(v1 - __half2float(h1)));
        *(unsigned*)(g_aol + ob1 + c) = pack2(__float2half_rn(v2 - __half2float(h2)),
                                              __float2half_rn(v3 - __half2float(h3)));
    }
}

// ---------------- host launcher ----------------
extern "C" void kernel_launch(void* const* d_in, const int* in_sizes, int n_in,
                              void* d_out, int out_size) {
    (void)in_sizes; (void)n_in; (void)out_size;
    const float* x    = (const float*)d_in[0];
    const float* Wqkv = (const float*)d_in[1];
    const float* bqkv = (const float*)d_in[2];
    const float* qn_w = (const float*)d_in[3];
    const float* kn_w = (const float*)d_in[4];
    const float* Wout = (const float*)d_in[5];
    const float* bout = (const float*)d_in[6];
    float* out = (float*)d_out;

    // [0] split x + fused RoPE table
    k_split_x<<<(MROWS * D_ / 4) / 256, 256>>>(x, MROWS * D_ / 4);
    // [1] split Wqkv
    k_split_w<<<(D_ * N3D / 4) / 256, 256>>>(Wqkv, 1, D_ * N3D / 4);

    // [2] QKV projection (3-term) + fused bias/rmsnorm/rope/split epilogue
    cudaFuncSetAttribute(k_gemm<0>, cudaFuncAttributeMaxDynamicSharedMemorySize, GEMM_SMEM);
    k_gemm<0><<<dim3(N3D / 128, MROWS / 256), 512, GEMM_SMEM>>>(bqkv, qn_w, kn_w, nullptr,
                                                                MROWS, N3D, D_);

    // [3] attention (ncu capture index) — K-lo/V-lo/P-lo dropped, Q-lo kept
    cudaFuncSetAttribute(k_attn, cudaFuncAttributeMaxDynamicSharedMemorySize, ATT_SMEM);
    k_attn<<<dim3(L_ / 128, B_ * H_), 256, ATT_SMEM>>>();

    // [4] split Wout (independent of attention; overlaps its tail)
    k_split_w<<<(D_ * D_ / 4) / 256, 256>>>(Wout, 2, D_ * D_ / 4);

    // [5] output projection (2-term: Wout-lo dropped) + bias -> d_out
    cudaFuncSetAttribute(k_gemm<1>, cudaFuncAttributeMaxDynamicSharedMemorySize, GEMM_SMEM);
    k_gemm<1><<<dim3(D_ / 128, MROWS / 256), 512, GEMM_SMEM>>>(bout, qn_w, kn_w, out,
                                                               MROWS, D_, D_);
}

// round 15
// speedup vs baseline: 1.6294x; 1.3271x over previous
#include <cuda_runtime.h>
#include <cuda_fp16.h>

// Problem constants
#define B_ 4
#define L_ 2048
#define D_ 1024
#define H_ 16
#define HD_ 64
#define MROWS 8192      // B*L
#define N3D 3072        // 3*D

// ---------------- device scratch (static allocation only) ----------------
__device__ __align__(16) __half g_xh[MROWS * D_];
__device__ __align__(16) __half g_xl[MROWS * D_];
__device__ __align__(16) __half g_wqh[D_ * N3D];   // [K][N] layout, hi only
__device__ __align__(16) __half g_woh[D_ * D_];    // hi only
__device__ __align__(16) __half g_q_hi[64 * 2048 * 64];
__device__ __align__(16) __half g_k_hi[64 * 2048 * 64];
__device__ __align__(16) __half g_v_hi[64 * 2048 * 64];
__device__ __align__(16) __half g_aoh[MROWS * D_];
__device__ __align__(16) __half g_aol[MROWS * D_];
__device__ __align__(16) float  g_cos[L_ * 32];
__device__ __align__(16) float  g_sin[L_ * 32];

// ---------------- PTX helpers ----------------
__device__ __forceinline__ void mma_fp16(float* d, const unsigned* a, unsigned b0, unsigned b1) {
    asm volatile(
        "mma.sync.aligned.m16n8k16.row.col.f32.f16.f16.f32 "
        "{%0,%1,%2,%3}, {%4,%5,%6,%7}, {%8,%9}, {%0,%1,%2,%3};\n"
        : "+f"(d[0]), "+f"(d[1]), "+f"(d[2]), "+f"(d[3])
        : "r"(a[0]), "r"(a[1]), "r"(a[2]), "r"(a[3]), "r"(b0), "r"(b1));
}
__device__ __forceinline__ void ldsm_x4(unsigned& r0, unsigned& r1, unsigned& r2, unsigned& r3, unsigned a) {
    asm volatile("ldmatrix.sync.aligned.m8n8.x4.shared.b16 {%0,%1,%2,%3}, [%4];\n"
                 : "=r"(r0), "=r"(r1), "=r"(r2), "=r"(r3) : "r"(a));
}
__device__ __forceinline__ void ldsm_x4t(unsigned& r0, unsigned& r1, unsigned& r2, unsigned& r3, unsigned a) {
    asm volatile("ldmatrix.sync.aligned.m8n8.x4.trans.shared.b16 {%0,%1,%2,%3}, [%4];\n"
                 : "=r"(r0), "=r"(r1), "=r"(r2), "=r"(r3) : "r"(a));
}
__device__ __forceinline__ void cp_async16(unsigned dst, const void* src) {
    asm volatile("cp.async.cg.shared.global [%0], [%1], 16;\n" :: "r"(dst), "l"(src));
}
__device__ __forceinline__ void cp_commit() { asm volatile("cp.async.commit_group;\n" ::: "memory"); }
template<int N> __device__ __forceinline__ void cp_wait() {
    asm volatile("cp.async.wait_group %0;\n" :: "n"(N) : "memory");
}
__device__ __forceinline__ unsigned pack2(__half a, __half b) {
    __half2 h = __halves2half2(a, b);
    return *reinterpret_cast<unsigned*>(&h);
}

// ---------------- x split (fp32 -> hi/lo halves) + fused RoPE table ----------------
__global__ void k_split_x(const float* __restrict__ src, int n4) {
    int i = blockIdx.x * blockDim.x + threadIdx.x;
    if (blockIdx.x < 256) {
        int idx = blockIdx.x * 256 + threadIdx.x;   // < 65536 = L_*32
        int l = idx >> 5, f = idx & 31;
        double invd = pow(10000.0, -(double)(2 * f) / 64.0);
        float invf = (float)invd;        // fp32 inv_freq matches jax value
        float ang = (float)l * invf;     // fp32 angle matches reference rounding
        double da = (double)ang;
        g_cos[idx] = (float)cos(da);
        g_sin[idx] = (float)sin(da);
    }
    if (i >= n4) return;
    float4 v = reinterpret_cast<const float4*>(src)[i];
    __half h0 = __float2half(v.x), h1 = __float2half(v.y);
    __half h2 = __float2half(v.z), h3 = __float2half(v.w);
    __half l0 = __float2half(v.x - __half2float(h0));
    __half l1 = __float2half(v.y - __half2float(h1));
    __half l2 = __float2half(v.z - __half2float(h2));
    __half l3 = __float2half(v.w - __half2float(h3));
    reinterpret_cast<__half2*>(g_xh)[2 * i]     = __halves2half2(h0, h1);
    reinterpret_cast<__half2*>(g_xh)[2 * i + 1] = __halves2half2(h2, h3);
    reinterpret_cast<__half2*>(g_xl)[2 * i]     = __halves2half2(l0, l1);
    reinterpret_cast<__half2*>(g_xl)[2 * i + 1] = __halves2half2(l2, l3);
}

// ---------------- weight convert (hi only; W-lo terms dropped) ----------------
__global__ void k_split_w(const float* __restrict__ src, int which, int n4) {
    __half* hi = (which == 1) ? g_wqh : g_woh;
    int i = blockIdx.x * blockDim.x + threadIdx.x;
    if (i >= n4) return;
    float4 v = reinterpret_cast<const float4*>(src)[i];
    reinterpret_cast<__half2*>(hi)[2 * i]     = __halves2half2(__float2half(v.x), __float2half(v.y));
    reinterpret_cast<__half2*>(hi)[2 * i + 1] = __halves2half2(__float2half(v.z), __float2half(v.w));
}

// ---------------- split-fp16 raw-mma GEMM, 512 threads, 256x128 tile, 3-stage ----------------
// Both GEMMs 2-term: C = Ah*Bh + Al*Bh  (weight residual dropped; input residual kept)
// WHICH==0: A=x(split), B=Wqkv(hi); fused epilogue: bias+rmsnorm+rope -> g_{q,k,v}_hi
// WHICH==1: A=attn_out(split), B=Wout(hi); epilogue: bias -> Cext fp32
#define GA_LD 40
#define GB_LD 136
#define G_AL (256 * GA_LD)              // 10240 halfs
#define G_BH (2 * 256 * GA_LD)          // 20480
#define G_STAGE (G_BH + 32 * GB_LD)     // 24832 halfs per stage
#define GEMM_SMEM (3 * G_STAGE * 2)     // 148992 bytes (epilogue staging reuses this)

template<int WHICH>
__device__ __forceinline__ void gemm_load_stage(unsigned smb, int s,
        const __half* Ah, const __half* Al, const __half* Bh,
        int m0, int n0, int k0, int N, int K, int tid) {
    unsigned sb = smb + (unsigned)(s * (G_STAGE * 2));
#pragma unroll
    for (int t = 0; t < 2; t++) {
        int c = tid + t * 512;              // 0..1023 chunks of A per array
        int ar = c >> 2, ac = (c & 3) * 8;
        unsigned da = sb + (unsigned)((ar * GA_LD + ac) * 2);
        cp_async16(da, Ah + (size_t)(m0 + ar) * K + k0 + ac);
        cp_async16(da + (unsigned)(G_AL * 2), Al + (size_t)(m0 + ar) * K + k0 + ac);
    }
    {
        int br = tid >> 4, bc = (tid & 15) * 8;   // 512 chunks of B
        unsigned db = sb + (unsigned)((G_BH + br * GB_LD + bc) * 2);
        cp_async16(db, Bh + (size_t)(k0 + br) * N + n0 + bc);
    }
}

template<int WHICH>
__global__ __launch_bounds__(512, 1) void k_gemm(const float* __restrict__ bias,
                                                 const float* __restrict__ qn_w,
                                                 const float* __restrict__ kn_w,
                                                 float* __restrict__ Cext,
                                                 int M, int N, int K) {
    extern __shared__ __align__(128) char sm_[];
    unsigned smb = (unsigned)__cvta_generic_to_shared(sm_);

    const __half* Ah = WHICH ? g_aoh : g_xh;
    const __half* Al = WHICH ? g_aol : g_xl;
    const __half* Bh = WHICH ? g_woh : g_wqh;

    int tid = threadIdx.x;
    int m0 = blockIdx.y * 256, n0 = blockIdx.x * 128;
    int wid = tid >> 5, lane = tid & 31;
    int wm = wid & 7, wn = wid >> 3;   // 8x2 warp grid; warp tile 32 rows x 64 cols

    float acc[2][8][4];                // [m16-tile][n8-tile][c-frag]
#pragma unroll
    for (int mi = 0; mi < 2; mi++)
#pragma unroll
        for (int g = 0; g < 8; g++)
#pragma unroll
            for (int r = 0; r < 4; r++) acc[mi][g][r] = 0.0f;

    gemm_load_stage<WHICH>(smb, 0, Ah, Al, Bh, m0, n0, 0,  N, K, tid); cp_commit();
    gemm_load_stage<WHICH>(smb, 1, Ah, Al, Bh, m0, n0, 32, N, K, tid); cp_commit();

    // ldmatrix lane addressing (constant per thread)
    int a_rofs = ((lane >> 3) & 1) * 8 + (lane & 7);   // row-within-16 provider
    int a_cofs = (lane >> 4) * 8;                      // k offset provider
    int b_rofs = ((lane >> 3) & 1) * 8 + (lane & 7);
    int b_cofs = ((lane >> 4) << 3);

    int niter = K / 32;
    for (int it = 0; it < niter; it++) {
        if (it < niter - 1) cp_wait<1>(); else cp_wait<0>();
        __syncthreads();
        int s = it - (it / 3) * 3;
        unsigned sb = smb + (unsigned)(s * (G_STAGE * 2));

#pragma unroll
        for (int kk = 0; kk < 32; kk += 16) {
            // A fragments: 2 m16-tiles, hi & lo
            unsigned ah[2][4], al[2][4];
#pragma unroll
            for (int mi = 0; mi < 2; mi++) {
                unsigned aaddr = sb + (unsigned)(((wm * 32 + mi * 16 + a_rofs) * GA_LD
                                                 + kk + a_cofs) * 2);
                ldsm_x4(ah[mi][0], ah[mi][1], ah[mi][2], ah[mi][3], aaddr);
                ldsm_x4(al[mi][0], al[mi][1], al[mi][2], al[mi][3],
                        aaddr + (unsigned)(G_AL * 2));
            }
            // B: 4 groups of n16, trans-ldmatrix from [k][n]
#pragma unroll
            for (int g = 0; g < 4; g++) {
                unsigned baddr = sb + (unsigned)((G_BH + (kk + b_rofs) * GB_LD
                                                  + wn * 64 + g * 16 + b_cofs) * 2);
                unsigned bh0, bh1, bh2, bh3;
                ldsm_x4t(bh0, bh1, bh2, bh3, baddr);
#pragma unroll
                for (int mi = 0; mi < 2; mi++) {
                    mma_fp16(acc[mi][2 * g],     ah[mi], bh0, bh1);
                    mma_fp16(acc[mi][2 * g],     al[mi], bh0, bh1);
                    mma_fp16(acc[mi][2 * g + 1], ah[mi], bh2, bh3);
                    mma_fp16(acc[mi][2 * g + 1], al[mi], bh2, bh3);
                }
            }
        }
        if (it + 2 < niter) {
            int s2 = (it + 2) - ((it + 2) / 3) * 3;
            gemm_load_stage<WHICH>(smb, s2, Ah, Al, Bh, m0, n0, (it + 2) * 32, N, K, tid);
            cp_commit();
        }
    }

    // ---- epilogue: stage warp tile (32x64) to smem, one lane per row ----
    __syncthreads();                       // pipeline smem free for staging
    float* st = (float*)sm_ + (size_t)wid * (32 * 68);
    {
        int cr = lane >> 2, cc = (lane & 3) * 2;
#pragma unroll
        for (int mi = 0; mi < 2; mi++)
#pragma unroll
            for (int g = 0; g < 8; g++) {
                st[(mi * 16 + cr) * 68 + g * 8 + cc]     = acc[mi][g][0];
                st[(mi * 16 + cr) * 68 + g * 8 + cc + 1] = acc[mi][g][1];
                st[(mi * 16 + cr + 8) * 68 + g * 8 + cc]     = acc[mi][g][2];
                st[(mi * 16 + cr + 8) * 68 + g * 8 + cc + 1] = acc[mi][g][3];
            }
    }
    __syncwarp();

    int gr = m0 + wm * 32 + lane;          // global row (lane owns one row)
    int gn0 = n0 + wn * 64;                // global col base (64-aligned => single head/matrix)
    float* rp = st + lane * 68;

    if (WHICH == 0) {
        int sel = gn0 >> 10;               // 0=Q, 1=K, 2=V
        int h = (gn0 & 1023) >> 6;
        int b = gr >> 11, l = gr & 2047;
        size_t dst = ((size_t)(b * 16 + h) * 2048 + l) * 64;

        if (sel == 2) {
#pragma unroll
            for (int c = 0; c < 64; c += 2) {
                float v0 = rp[c]     + bias[gn0 + c];
                float v1 = rp[c + 1] + bias[gn0 + c + 1];
                *(unsigned*)(g_v_hi + dst + c) = pack2(__float2half(v0), __float2half(v1));
            }
        } else {
            const float* w = (sel == 0) ? qn_w : kn_w;
            __half* hp = (sel == 0) ? g_q_hi : g_k_hi;
            float ss = 0.f;
#pragma unroll
            for (int c = 0; c < 64; c++) {
                float v = rp[c] + bias[gn0 + c];
                rp[c] = v;
                ss += v * v;
            }
            float rms = rsqrtf(ss * (1.0f / 64.0f) + 1e-6f);
            float qs = (sel == 0) ? 0.125f : 1.0f;   // fold attn scale into Q
#pragma unroll
            for (int c = 0; c < 32; c += 2) {
                float cv0 = g_cos[l * 32 + c],     sv0 = g_sin[l * 32 + c];
                float cv1 = g_cos[l * 32 + c + 1], sv1 = g_sin[l * 32 + c + 1];
                float t10 = rp[c]      * rms * w[c];
                float t11 = rp[c + 1]  * rms * w[c + 1];
                float t20 = rp[c + 32] * rms * w[c + 32];
                float t21 = rp[c + 33] * rms * w[c + 33];
                float o10 = (t10 * cv0 - t20 * sv0) * qs;
                float o11 = (t11 * cv1 - t21 * sv1) * qs;
                float o20 = (t10 * sv0 + t20 * cv0) * qs;
                float o21 = (t11 * sv1 + t21 * cv1) * qs;
                *(unsigned*)(hp + dst + c)      = pack2(__float2half(o10), __float2half(o11));
                *(unsigned*)(hp + dst + 32 + c) = pack2(__float2half(o20), __float2half(o21));
            }
        }
    } else {
        float* dst = Cext + (size_t)gr * N + gn0;
#pragma unroll
        for (int c = 0; c < 64; c += 4) {
            float4 v;
            v.x = rp[c]     + bias[gn0 + c];
            v.y = rp[c + 1] + bias[gn0 + c + 1];
            v.z = rp[c + 2] + bias[gn0 + c + 2];
            v.w = rp[c + 3] + bias[gn0 + c + 3];
            *reinterpret_cast<float4*>(dst + c) = v;
        }
    }
}

// ---------------- FA2-style flash attention, pure fp16 MMA, 3-stage cp.async ----------------
// S = Qh*Kh; PV = Ph*Vh. fp32 online softmax. Residual corrections live in the GEMMs.
#define ATT_LD 72
#define ATT_TILE (64 * ATT_LD)
#define ATT_STAGE (2 * ATT_TILE)        // Kh + Vh
#define ATT_SMEM (3 * ATT_STAGE * 2)    // 55296 bytes

__device__ __forceinline__ void att_load_tile(unsigned smb, size_t gbase, int j, int s, int tid) {
    const __half* src0 = g_k_hi + gbase;
    const __half* src1 = g_v_hi + gbase;
#pragma unroll
    for (int t = 0; t < 2; t++) {
        int c = tid + t * 256;
        int row = c >> 3, col = (c & 7) * 8;
        size_t goff = (size_t)(j * 64 + row) * 64 + col;
        unsigned d = smb + (unsigned)((s * ATT_STAGE + row * ATT_LD + col) * 2);
        cp_async16(d,                            src0 + goff);
        cp_async16(d + (unsigned)(ATT_TILE * 2), src1 + goff);
    }
}

__global__ __launch_bounds__(256, 1) void k_attn() {
    extern __shared__ __align__(128) char sm_[];
    unsigned smb = (unsigned)__cvta_generic_to_shared(sm_);

    int tid = threadIdx.x, lane = tid & 31, wid = tid >> 5;
    int bh = blockIdx.y;
    size_t gbase = (size_t)bh * (2048 * 64);
    int q0 = blockIdx.x * 128 + wid * 16;

    unsigned qf[4][4];
    {
        const __half* Qh = g_q_hi + gbase;
        int r0 = q0 + (lane >> 2);
        int cb = (lane & 3) * 2;
#pragma unroll
        for (int kk = 0; kk < 4; kk++) {
            int c = kk * 16 + cb;
            qf[kk][0] = *(const unsigned*)(Qh + (size_t)r0 * 64 + c);
            qf[kk][1] = *(const unsigned*)(Qh + (size_t)(r0 + 8) * 64 + c);
            qf[kk][2] = *(const unsigned*)(Qh + (size_t)r0 * 64 + c + 8);
            qf[kk][3] = *(const unsigned*)(Qh + (size_t)(r0 + 8) * 64 + c + 8);
        }
    }

    float oacc[8][4];
#pragma unroll
    for (int t = 0; t < 8; t++) { oacc[t][0] = 0.f; oacc[t][1] = 0.f; oacc[t][2] = 0.f; oacc[t][3] = 0.f; }
    float m0 = -1e30f, m1 = -1e30f, l0 = 0.f, l1 = 0.f;

    att_load_tile(smb, gbase, 0, 0, tid); cp_commit();
    att_load_tile(smb, gbase, 1, 1, tid); cp_commit();

    for (int j = 0; j < 32; j++) {
        int s = j - (j / 3) * 3;
        if (j < 31) cp_wait<1>(); else cp_wait<0>();
        __syncthreads();

        unsigned kbase = smb + (unsigned)(s * ATT_STAGE * 2);
        unsigned vbase = kbase + (unsigned)(ATT_TILE * 2);

        float sacc[8][4];
#pragma unroll
        for (int t = 0; t < 8; t++) { sacc[t][0] = 0.f; sacc[t][1] = 0.f; sacc[t][2] = 0.f; sacc[t][3] = 0.f; }
#pragma unroll
        for (int kk = 0; kk < 4; kk++) {
#pragma unroll
            for (int p = 0; p < 4; p++) {
                int row = p * 16 + ((lane >> 4) << 3) + (lane & 7);
                int col = kk * 16 + ((lane >> 3) & 1) * 8;
                unsigned addr = kbase + (unsigned)((row * ATT_LD + col) * 2);
                unsigned kh0, kh1, kh2, kh3;
                ldsm_x4(kh0, kh1, kh2, kh3, addr);
                mma_fp16(sacc[2 * p],     qf[kk], kh0, kh1);
                mma_fp16(sacc[2 * p + 1], qf[kk], kh2, kh3);
            }
        }

        float mx0 = -1e30f, mx1 = -1e30f;
#pragma unroll
        for (int t = 0; t < 8; t++) {
            mx0 = fmaxf(mx0, fmaxf(sacc[t][0], sacc[t][1]));
            mx1 = fmaxf(mx1, fmaxf(sacc[t][2], sacc[t][3]));
        }
        mx0 = fmaxf(mx0, __shfl_xor_sync(0xffffffffu, mx0, 1));
        mx0 = fmaxf(mx0, __shfl_xor_sync(0xffffffffu, mx0, 2));
        mx1 = fmaxf(mx1, __shfl_xor_sync(0xffffffffu, mx1, 1));
        mx1 = fmaxf(mx1, __shfl_xor_sync(0xffffffffu, mx1, 2));
        float mn0 = fmaxf(m0, mx0), mn1 = fmaxf(m1, mx1);
        float c0 = __expf(m0 - mn0), c1 = __expf(m1 - mn1);
        m0 = mn0; m1 = mn1;

        float ls0 = 0.f, ls1 = 0.f;
        unsigned pf[4][4];   // P hi only
#pragma unroll
        for (int p = 0; p < 4; p++) {
#pragma unroll
            for (int u = 0; u < 2; u++) {
                int t = 2 * p + u;
                float e0 = __expf(sacc[t][0] - mn0);
                float e1 = __expf(sacc[t][1] - mn0);
                float e2 = __expf(sacc[t][2] - mn1);
                float e3 = __expf(sacc[t][3] - mn1);
                ls0 += e0 + e1; ls1 += e2 + e3;
                pf[p][2 * u]     = pack2(__float2half_rn(e0), __float2half_rn(e1));
                pf[p][2 * u + 1] = pack2(__float2half_rn(e2), __float2half_rn(e3));
            }
        }
        ls0 += __shfl_xor_sync(0xffffffffu, ls0, 1);
        ls0 += __shfl_xor_sync(0xffffffffu, ls0, 2);
        ls1 += __shfl_xor_sync(0xffffffffu, ls1, 1);
        ls1 += __shfl_xor_sync(0xffffffffu, ls1, 2);
        l0 = l0 * c0 + ls0;
        l1 = l1 * c1 + ls1;
#pragma unroll
        for (int t = 0; t < 8; t++) { oacc[t][0] *= c0; oacc[t][1] *= c0; oacc[t][2] *= c1; oacc[t][3] *= c1; }

#pragma unroll
        for (int kk = 0; kk < 4; kk++) {
#pragma unroll
            for (int t2 = 0; t2 < 4; t2++) {
                int row = kk * 16 + ((lane >> 3) & 1) * 8 + (lane & 7);
                int col = t2 * 16 + ((lane >> 4) << 3);
                unsigned addr = vbase + (unsigned)((row * ATT_LD + col) * 2);
                unsigned vh0, vh1, vh2, vh3;
                ldsm_x4t(vh0, vh1, vh2, vh3, addr);
                mma_fp16(oacc[2 * t2],     pf[kk], vh0, vh1);
                mma_fp16(oacc[2 * t2 + 1], pf[kk], vh2, vh3);
            }
        }

        if (j + 2 < 32) {
            int s2 = (j + 2) - ((j + 2) / 3) * 3;
            att_load_tile(smb, gbase, j + 2, s2, tid);
            cp_commit();
        }
    }

    float i0 = 1.0f / l0, i1 = 1.0f / l1;
    int b = bh >> 4, h = bh & 15;
    int r = q0 + (lane >> 2);
    size_t ob0 = (size_t)(b * 2048 + r) * 1024 + h * 64;
    size_t ob1 = ob0 + (size_t)8 * 1024;
#pragma unroll
    for (int t = 0; t < 8; t++) {
        int c = t * 8 + (lane & 3) * 2;
        float v0 = oacc[t][0] * i0, v1 = oacc[t][1] * i0;
        float v2 = oacc[t][2] * i1, v3 = oacc[t][3] * i1;
        __half h0 = __float2half_rn(v0), h1 = __float2half_rn(v1);
        __half h2 = __float2half_rn(v2), h3 = __float2half_rn(v3);
        *(unsigned*)(g_aoh + ob0 + c) = pack2(h0, h1);
        *(unsigned*)(g_aoh + ob1 + c) = pack2(h2, h3);
        *(unsigned*)(g_aol + ob0 + c) = pack2(__float2half_rn(v0 - __half2float(h0)),
                                              __float2half_rn(v1 - __half2float(h1)));
        *(unsigned*)(g_aol + ob1 + c) = pack2(__float2half_rn(v2 - __half2float(h2)),
                                              __float2half_rn(v3 - __half2float(h3)));
    }
}

// ---------------- host launcher ----------------
extern "C" void kernel_launch(void* const* d_in, const int* in_sizes, int n_in,
                              void* d_out, int out_size) {
    (void)in_sizes; (void)n_in; (void)out_size;
    const float* x    = (const float*)d_in[0];
    const float* Wqkv = (const float*)d_in[1];
    const float* bqkv = (const float*)d_in[2];
    const float* qn_w = (const float*)d_in[3];
    const float* kn_w = (const float*)d_in[4];
    const float* Wout = (const float*)d_in[5];
    const float* bout = (const float*)d_in[6];
    float* out = (float*)d_out;

    // [0] split x + fused RoPE table
    k_split_x<<<(MROWS * D_ / 4) / 256, 256>>>(x, MROWS * D_ / 4);
    // [1] convert Wqkv (hi only)
    k_split_w<<<(D_ * N3D / 4) / 256, 256>>>(Wqkv, 1, D_ * N3D / 4);

    // [2] QKV projection (2-term) + fused bias/rmsnorm/rope epilogue
    cudaFuncSetAttribute(k_gemm<0>, cudaFuncAttributeMaxDynamicSharedMemorySize, GEMM_SMEM);
    k_gemm<0><<<dim3(N3D / 128, MROWS / 256), 512, GEMM_SMEM>>>(bqkv, qn_w, kn_w, nullptr,
                                                                MROWS, N3D, D_);

    // [3] attention (ncu capture index) — pure fp16 MMA, fp32 softmax
    cudaFuncSetAttribute(k_attn, cudaFuncAttributeMaxDynamicSharedMemorySize, ATT_SMEM);
    k_attn<<<dim3(L_ / 128, B_ * H_), 256, ATT_SMEM>>>();

    // [4] convert Wout (hi only; independent of attention, overlaps its tail)
    k_split_w<<<(D_ * D_ / 4) / 256, 256>>>(Wout, 2, D_ * D_ / 4);

    // [5] output projection (2-term) + bias -> d_out
    cudaFuncSetAttribute(k_gemm<1>, cudaFuncAttributeMaxDynamicSharedMemorySize, GEMM_SMEM);
    k_gemm<1><<<dim3(D_ / 128, MROWS / 256), 512, GEMM_SMEM>>>(bout, qn_w, kn_w, out,
                                                               MROWS, D_, D_);
}

// round 16
// speedup vs baseline: 1.9691x; 1.2085x over previous
#include <cuda_runtime.h>
#include <cuda_fp16.h>

// Problem constants
#define B_ 4
#define L_ 2048
#define D_ 1024
#define H_ 16
#define HD_ 64
#define MROWS 8192      // B*L
#define N3D 3072        // 3*D
#define LOG2E_ 1.44269504088896340736f

// ---------------- device scratch (static allocation only) ----------------
__device__ __align__(16) __half g_xh[MROWS * D_];
__device__ __align__(16) __half g_wqh[D_ * N3D];   // [K][N] layout, hi only
__device__ __align__(16) __half g_woh[D_ * D_];    // hi only
__device__ __align__(16) __half g_q_hi[64 * 2048 * 64];
__device__ __align__(16) __half g_k_hi[64 * 2048 * 64];
__device__ __align__(16) __half g_v_hi[64 * 2048 * 64];
__device__ __align__(16) __half g_aoh[MROWS * D_];
__device__ __align__(16) __half g_aol[MROWS * D_];
__device__ __align__(16) float  g_cos[L_ * 32];
__device__ __align__(16) float  g_sin[L_ * 32];

// ---------------- PTX helpers ----------------
__device__ __forceinline__ void mma_fp16(float* d, const unsigned* a, unsigned b0, unsigned b1) {
    asm volatile(
        "mma.sync.aligned.m16n8k16.row.col.f32.f16.f16.f32 "
        "{%0,%1,%2,%3}, {%4,%5,%6,%7}, {%8,%9}, {%0,%1,%2,%3};\n"
        : "+f"(d[0]), "+f"(d[1]), "+f"(d[2]), "+f"(d[3])
        : "r"(a[0]), "r"(a[1]), "r"(a[2]), "r"(a[3]), "r"(b0), "r"(b1));
}
__device__ __forceinline__ void ldsm_x4(unsigned& r0, unsigned& r1, unsigned& r2, unsigned& r3, unsigned a) {
    asm volatile("ldmatrix.sync.aligned.m8n8.x4.shared.b16 {%0,%1,%2,%3}, [%4];\n"
                 : "=r"(r0), "=r"(r1), "=r"(r2), "=r"(r3) : "r"(a));
}
__device__ __forceinline__ void ldsm_x4t(unsigned& r0, unsigned& r1, unsigned& r2, unsigned& r3, unsigned a) {
    asm volatile("ldmatrix.sync.aligned.m8n8.x4.trans.shared.b16 {%0,%1,%2,%3}, [%4];\n"
                 : "=r"(r0), "=r"(r1), "=r"(r2), "=r"(r3) : "r"(a));
}
__device__ __forceinline__ void cp_async16(unsigned dst, const void* src) {
    asm volatile("cp.async.cg.shared.global [%0], [%1], 16;\n" :: "r"(dst), "l"(src));
}
__device__ __forceinline__ void cp_commit() { asm volatile("cp.async.commit_group;\n" ::: "memory"); }
template<int N> __device__ __forceinline__ void cp_wait() {
    asm volatile("cp.async.wait_group %0;\n" :: "n"(N) : "memory");
}
__device__ __forceinline__ unsigned pack2(__half a, __half b) {
    __half2 h = __halves2half2(a, b);
    return *reinterpret_cast<unsigned*>(&h);
}
__device__ __forceinline__ unsigned packf2(float a, float b) {
    __half2 h = __floats2half2_rn(a, b);   // single cvt.rn.f16x2.f32
    return *reinterpret_cast<unsigned*>(&h);
}

// ---------------- x convert (fp16 hi only) + fused RoPE table ----------------
__global__ void k_split_x(const float* __restrict__ src, int n4) {
    int i = blockIdx.x * blockDim.x + threadIdx.x;
    if (blockIdx.x < 256) {
        int idx = blockIdx.x * 256 + threadIdx.x;   // < 65536 = L_*32
        int l = idx >> 5, f = idx & 31;
        double invd = pow(10000.0, -(double)(2 * f) / 64.0);
        float invf = (float)invd;        // fp32 inv_freq matches jax value
        float ang = (float)l * invf;     // fp32 angle matches reference rounding
        double da = (double)ang;
        g_cos[idx] = (float)cos(da);
        g_sin[idx] = (float)sin(da);
    }
    if (i >= n4) return;
    float4 v = reinterpret_cast<const float4*>(src)[i];
    reinterpret_cast<__half2*>(g_xh)[2 * i]     = __floats2half2_rn(v.x, v.y);
    reinterpret_cast<__half2*>(g_xh)[2 * i + 1] = __floats2half2_rn(v.z, v.w);
}

// ---------------- weight convert (hi only) ----------------
__global__ void k_split_w(const float* __restrict__ src, int which, int n4) {
    __half* hi = (which == 1) ? g_wqh : g_woh;
    int i = blockIdx.x * blockDim.x + threadIdx.x;
    if (i >= n4) return;
    float4 v = reinterpret_cast<const float4*>(src)[i];
    reinterpret_cast<__half2*>(hi)[2 * i]     = __floats2half2_rn(v.x, v.y);
    reinterpret_cast<__half2*>(hi)[2 * i + 1] = __floats2half2_rn(v.z, v.w);
}

// ---------------- raw-mma GEMM, 512 threads, 256x128 tile, 3-stage ----------------
// WHICH==0: pure fp16, A=x(hi), B=Wqkv(hi); fused epilogue: bias+rmsnorm+rope -> g_{q,k,v}_hi
// WHICH==1: 2-term (input residual kept): A=attn_out(hi,lo), B=Wout(hi); epilogue: bias -> fp32
#define GA_LD 40
#define GB_LD 136
#define G_AL (256 * GA_LD)              // A-lo region (WHICH==1 only)
#define G_BH (2 * 256 * GA_LD)          // 20480
#define G_STAGE (G_BH + 32 * GB_LD)     // 24832 halfs per stage
#define GEMM_SMEM (3 * G_STAGE * 2)     // 148992 bytes (epilogue staging reuses this)

template<int WHICH>
__device__ __forceinline__ void gemm_load_stage(unsigned smb, int s,
        const __half* Ah, const __half* Al, const __half* Bh,
        int m0, int n0, int k0, int N, int K, int tid) {
    unsigned sb = smb + (unsigned)(s * (G_STAGE * 2));
#pragma unroll
    for (int t = 0; t < 2; t++) {
        int c = tid + t * 512;              // 0..1023 chunks of A per array
        int ar = c >> 2, ac = (c & 3) * 8;
        unsigned da = sb + (unsigned)((ar * GA_LD + ac) * 2);
        cp_async16(da, Ah + (size_t)(m0 + ar) * K + k0 + ac);
        if (WHICH == 1)
            cp_async16(da + (unsigned)(G_AL * 2), Al + (size_t)(m0 + ar) * K + k0 + ac);
    }
    {
        int br = tid >> 4, bc = (tid & 15) * 8;   // 512 chunks of B
        unsigned db = sb + (unsigned)((G_BH + br * GB_LD + bc) * 2);
        cp_async16(db, Bh + (size_t)(k0 + br) * N + n0 + bc);
    }
}

template<int WHICH>
__global__ __launch_bounds__(512, 1) void k_gemm(const float* __restrict__ bias,
                                                 const float* __restrict__ qn_w,
                                                 const float* __restrict__ kn_w,
                                                 float* __restrict__ Cext,
                                                 int M, int N, int K) {
    extern __shared__ __align__(128) char sm_[];
    unsigned smb = (unsigned)__cvta_generic_to_shared(sm_);

    const __half* Ah = WHICH ? g_aoh : g_xh;
    const __half* Al = WHICH ? g_aol : g_xh;   // dummy for WHICH==0 (never loaded)
    const __half* Bh = WHICH ? g_woh : g_wqh;

    int tid = threadIdx.x;
    int m0 = blockIdx.y * 256, n0 = blockIdx.x * 128;
    int wid = tid >> 5, lane = tid & 31;
    int wm = wid & 7, wn = wid >> 3;   // 8x2 warp grid; warp tile 32 rows x 64 cols

    float acc[2][8][4];                // [m16-tile][n8-tile][c-frag]
#pragma unroll
    for (int mi = 0; mi < 2; mi++)
#pragma unroll
        for (int g = 0; g < 8; g++)
#pragma unroll
            for (int r = 0; r < 4; r++) acc[mi][g][r] = 0.0f;

    gemm_load_stage<WHICH>(smb, 0, Ah, Al, Bh, m0, n0, 0,  N, K, tid); cp_commit();
    gemm_load_stage<WHICH>(smb, 1, Ah, Al, Bh, m0, n0, 32, N, K, tid); cp_commit();

    // ldmatrix lane addressing (constant per thread)
    int a_rofs = ((lane >> 3) & 1) * 8 + (lane & 7);   // row-within-16 provider
    int a_cofs = (lane >> 4) * 8;                      // k offset provider
    int b_rofs = ((lane >> 3) & 1) * 8 + (lane & 7);
    int b_cofs = ((lane >> 4) << 3);

    int niter = K / 32;
    for (int it = 0; it < niter; it++) {
        if (it < niter - 1) cp_wait<1>(); else cp_wait<0>();
        __syncthreads();
        int s = it - (it / 3) * 3;
        unsigned sb = smb + (unsigned)(s * (G_STAGE * 2));

#pragma unroll
        for (int kk = 0; kk < 32; kk += 16) {
            unsigned ah[2][4], al[2][4];
#pragma unroll
            for (int mi = 0; mi < 2; mi++) {
                unsigned aaddr = sb + (unsigned)(((wm * 32 + mi * 16 + a_rofs) * GA_LD
                                                 + kk + a_cofs) * 2);
                ldsm_x4(ah[mi][0], ah[mi][1], ah[mi][2], ah[mi][3], aaddr);
                if (WHICH == 1)
                    ldsm_x4(al[mi][0], al[mi][1], al[mi][2], al[mi][3],
                            aaddr + (unsigned)(G_AL * 2));
            }
#pragma unroll
            for (int g = 0; g < 4; g++) {
                unsigned baddr = sb + (unsigned)((G_BH + (kk + b_rofs) * GB_LD
                                                  + wn * 64 + g * 16 + b_cofs) * 2);
                unsigned bh0, bh1, bh2, bh3;
                ldsm_x4t(bh0, bh1, bh2, bh3, baddr);
#pragma unroll
                for (int mi = 0; mi < 2; mi++) {
                    mma_fp16(acc[mi][2 * g],     ah[mi], bh0, bh1);
                    if (WHICH == 1) mma_fp16(acc[mi][2 * g], al[mi], bh0, bh1);
                    mma_fp16(acc[mi][2 * g + 1], ah[mi], bh2, bh3);
                    if (WHICH == 1) mma_fp16(acc[mi][2 * g + 1], al[mi], bh2, bh3);
                }
            }
        }
        if (it + 2 < niter) {
            int s2 = (it + 2) - ((it + 2) / 3) * 3;
            gemm_load_stage<WHICH>(smb, s2, Ah, Al, Bh, m0, n0, (it + 2) * 32, N, K, tid);
            cp_commit();
        }
    }

    // ---- epilogue: stage warp tile (32x64) to smem, one lane per row ----
    __syncthreads();                       // pipeline smem free for staging
    float* st = (float*)sm_ + (size_t)wid * (32 * 68);
    {
        int cr = lane >> 2, cc = (lane & 3) * 2;
#pragma unroll
        for (int mi = 0; mi < 2; mi++)
#pragma unroll
            for (int g = 0; g < 8; g++) {
                st[(mi * 16 + cr) * 68 + g * 8 + cc]     = acc[mi][g][0];
                st[(mi * 16 + cr) * 68 + g * 8 + cc + 1] = acc[mi][g][1];
                st[(mi * 16 + cr + 8) * 68 + g * 8 + cc]     = acc[mi][g][2];
                st[(mi * 16 + cr + 8) * 68 + g * 8 + cc + 1] = acc[mi][g][3];
            }
    }
    __syncwarp();

    int gr = m0 + wm * 32 + lane;          // global row (lane owns one row)
    int gn0 = n0 + wn * 64;                // global col base (64-aligned => single head/matrix)
    float* rp = st + lane * 68;

    if (WHICH == 0) {
        int sel = gn0 >> 10;               // 0=Q, 1=K, 2=V
        int h = (gn0 & 1023) >> 6;
        int b = gr >> 11, l = gr & 2047;
        size_t dst = ((size_t)(b * 16 + h) * 2048 + l) * 64;

        if (sel == 2) {
#pragma unroll
            for (int c = 0; c < 64; c += 2) {
                float v0 = rp[c]     + bias[gn0 + c];
                float v1 = rp[c + 1] + bias[gn0 + c + 1];
                *(unsigned*)(g_v_hi + dst + c) = packf2(v0, v1);
            }
        } else {
            const float* w = (sel == 0) ? qn_w : kn_w;
            __half* hp = (sel == 0) ? g_q_hi : g_k_hi;
            float ss = 0.f;
#pragma unroll
            for (int c = 0; c < 64; c++) {
                float v = rp[c] + bias[gn0 + c];
                rp[c] = v;
                ss += v * v;
            }
            float rms = rsqrtf(ss * (1.0f / 64.0f) + 1e-6f);
            // Q: fold attn scale AND log2(e) so softmax can run in exp2 domain
            float qs = (sel == 0) ? (0.125f * LOG2E_) : 1.0f;
#pragma unroll
            for (int c = 0; c < 32; c += 2) {
                float cv0 = g_cos[l * 32 + c],     sv0 = g_sin[l * 32 + c];
                float cv1 = g_cos[l * 32 + c + 1], sv1 = g_sin[l * 32 + c + 1];
                float t10 = rp[c]      * rms * w[c];
                float t11 = rp[c + 1]  * rms * w[c + 1];
                float t20 = rp[c + 32] * rms * w[c + 32];
                float t21 = rp[c + 33] * rms * w[c + 33];
                float o10 = (t10 * cv0 - t20 * sv0) * qs;
                float o11 = (t11 * cv1 - t21 * sv1) * qs;
                float o20 = (t10 * sv0 + t20 * cv0) * qs;
                float o21 = (t11 * sv1 + t21 * cv1) * qs;
                *(unsigned*)(hp + dst + c)      = packf2(o10, o11);
                *(unsigned*)(hp + dst + 32 + c) = packf2(o20, o21);
            }
        }
    } else {
        float* dst = Cext + (size_t)gr * N + gn0;
#pragma unroll
        for (int c = 0; c < 64; c += 4) {
            float4 v;
            v.x = rp[c]     + bias[gn0 + c];
            v.y = rp[c + 1] + bias[gn0 + c + 1];
            v.z = rp[c + 2] + bias[gn0 + c + 2];
            v.w = rp[c + 3] + bias[gn0 + c + 3];
            *reinterpret_cast<float4*>(dst + c) = v;
        }
    }
}

// ---------------- FA2-style flash attention, pure fp16 MMA, exp2-domain softmax ----------------
// S (already scaled by log2e via Q); P = exp2(S - m). Numerically identical softmax weights.
#define ATT_LD 72
#define ATT_TILE (64 * ATT_LD)
#define ATT_STAGE (2 * ATT_TILE)        // Kh + Vh
#define ATT_SMEM (3 * ATT_STAGE * 2)    // 55296 bytes

__device__ __forceinline__ void att_load_tile(unsigned smb, size_t gbase, int j, int s, int tid) {
    const __half* src0 = g_k_hi + gbase;
    const __half* src1 = g_v_hi + gbase;
#pragma unroll
    for (int t = 0; t < 2; t++) {
        int c = tid + t * 256;
        int row = c >> 3, col = (c & 7) * 8;
        size_t goff = (size_t)(j * 64 + row) * 64 + col;
        unsigned d = smb + (unsigned)((s * ATT_STAGE + row * ATT_LD + col) * 2);
        cp_async16(d,                            src0 + goff);
        cp_async16(d + (unsigned)(ATT_TILE * 2), src1 + goff);
    }
}

__global__ __launch_bounds__(256, 1) void k_attn() {
    extern __shared__ __align__(128) char sm_[];
    unsigned smb = (unsigned)__cvta_generic_to_shared(sm_);

    int tid = threadIdx.x, lane = tid & 31, wid = tid >> 5;
    int bh = blockIdx.y;
    size_t gbase = (size_t)bh * (2048 * 64);
    int q0 = blockIdx.x * 128 + wid * 16;

    unsigned qf[4][4];
    {
        const __half* Qh = g_q_hi + gbase;
        int r0 = q0 + (lane >> 2);
        int cb = (lane & 3) * 2;
#pragma unroll
        for (int kk = 0; kk < 4; kk++) {
            int c = kk * 16 + cb;
            qf[kk][0] = *(const unsigned*)(Qh + (size_t)r0 * 64 + c);
            qf[kk][1] = *(const unsigned*)(Qh + (size_t)(r0 + 8) * 64 + c);
            qf[kk][2] = *(const unsigned*)(Qh + (size_t)r0 * 64 + c + 8);
            qf[kk][3] = *(const unsigned*)(Qh + (size_t)(r0 + 8) * 64 + c + 8);
        }
    }

    float oacc[8][4];
#pragma unroll
    for (int t = 0; t < 8; t++) { oacc[t][0] = 0.f; oacc[t][1] = 0.f; oacc[t][2] = 0.f; oacc[t][3] = 0.f; }
    float m0 = -1e30f, m1 = -1e30f, l0 = 0.f, l1 = 0.f;

    att_load_tile(smb, gbase, 0, 0, tid); cp_commit();
    att_load_tile(smb, gbase, 1, 1, tid); cp_commit();

    for (int j = 0; j < 32; j++) {
        int s = j - (j / 3) * 3;
        if (j < 31) cp_wait<1>(); else cp_wait<0>();
        __syncthreads();

        unsigned kbase = smb + (unsigned)(s * ATT_STAGE * 2);
        unsigned vbase = kbase + (unsigned)(ATT_TILE * 2);

        float sacc[8][4];
#pragma unroll
        for (int t = 0; t < 8; t++) { sacc[t][0] = 0.f; sacc[t][1] = 0.f; sacc[t][2] = 0.f; sacc[t][3] = 0.f; }
#pragma unroll
        for (int kk = 0; kk < 4; kk++) {
#pragma unroll
            for (int p = 0; p < 4; p++) {
                int row = p * 16 + ((lane >> 4) << 3) + (lane & 7);
                int col = kk * 16 + ((lane >> 3) & 1) * 8;
                unsigned addr = kbase + (unsigned)((row * ATT_LD + col) * 2);
                unsigned kh0, kh1, kh2, kh3;
                ldsm_x4(kh0, kh1, kh2, kh3, addr);
                mma_fp16(sacc[2 * p],     qf[kk], kh0, kh1);
                mma_fp16(sacc[2 * p + 1], qf[kk], kh2, kh3);
            }
        }

        float mx0 = -1e30f, mx1 = -1e30f;
#pragma unroll
        for (int t = 0; t < 8; t++) {
            mx0 = fmaxf(mx0, fmaxf(sacc[t][0], sacc[t][1]));
            mx1 = fmaxf(mx1, fmaxf(sacc[t][2], sacc[t][3]));
        }
        mx0 = fmaxf(mx0, __shfl_xor_sync(0xffffffffu, mx0, 1));
        mx0 = fmaxf(mx0, __shfl_xor_sync(0xffffffffu, mx0, 2));
        mx1 = fmaxf(mx1, __shfl_xor_sync(0xffffffffu, mx1, 1));
        mx1 = fmaxf(mx1, __shfl_xor_sync(0xffffffffu, mx1, 2));
        float mn0 = fmaxf(m0, mx0), mn1 = fmaxf(m1, mx1);
        float c0 = exp2f(m0 - mn0), c1 = exp2f(m1 - mn1);
        m0 = mn0; m1 = mn1;

        float ls0 = 0.f, ls1 = 0.f;
        unsigned pf[4][4];   // P hi only
#pragma unroll
        for (int p = 0; p < 4; p++) {
#pragma unroll
            for (int u = 0; u < 2; u++) {
                int t = 2 * p + u;
                float e0 = exp2f(sacc[t][0] - mn0);
                float e1 = exp2f(sacc[t][1] - mn0);
                float e2 = exp2f(sacc[t][2] - mn1);
                float e3 = exp2f(sacc[t][3] - mn1);
                ls0 += e0 + e1; ls1 += e2 + e3;
                pf[p][2 * u]     = packf2(e0, e1);
                pf[p][2 * u + 1] = packf2(e2, e3);
            }
        }
        ls0 += __shfl_xor_sync(0xffffffffu, ls0, 1);
        ls0 += __shfl_xor_sync(0xffffffffu, ls0, 2);
        ls1 += __shfl_xor_sync(0xffffffffu, ls1, 1);
        ls1 += __shfl_xor_sync(0xffffffffu, ls1, 2);
        l0 = l0 * c0 + ls0;
        l1 = l1 * c1 + ls1;
#pragma unroll
        for (int t = 0; t < 8; t++) { oacc[t][0] *= c0; oacc[t][1] *= c0; oacc[t][2] *= c1; oacc[t][3] *= c1; }

#pragma unroll
        for (int kk = 0; kk < 4; kk++) {
#pragma unroll
            for (int t2 = 0; t2 < 4; t2++) {
                int row = kk * 16 + ((lane >> 3) & 1) * 8 + (lane & 7);
                int col = t2 * 16 + ((lane >> 4) << 3);
                unsigned addr = vbase + (unsigned)((row * ATT_LD + col) * 2);
                unsigned vh0, vh1, vh2, vh3;
                ldsm_x4t(vh0, vh1, vh2, vh3, addr);
                mma_fp16(oacc[2 * t2],     pf[kk], vh0, vh1);
                mma_fp16(oacc[2 * t2 + 1], pf[kk], vh2, vh3);
            }
        }

        if (j + 2 < 32) {
            int s2 = (j + 2) - ((j + 2) / 3) * 3;
            att_load_tile(smb, gbase, j + 2, s2, tid);
            cp_commit();
        }
    }

    float i0 = 1.0f / l0, i1 = 1.0f / l1;
    int b = bh >> 4, h = bh & 15;
    int r = q0 + (lane >> 2);
    size_t ob0 = (size_t)(b * 2048 + r) * 1024 + h * 64;
    size_t ob1 = ob0 + (size_t)8 * 1024;
#pragma unroll
    for (int t = 0; t < 8; t++) {
        int c = t * 8 + (lane & 3) * 2;
        float v0 = oacc[t][0] * i0, v1 = oacc[t][1] * i0;
        float v2 = oacc[t][2] * i1, v3 = oacc[t][3] * i1;
        __half h0 = __float2half_rn(v0), h1 = __float2half_rn(v1);
        __half h2 = __float2half_rn(v2), h3 = __float2half_rn(v3);
        *(unsigned*)(g_aoh + ob0 + c) = pack2(h0, h1);
        *(unsigned*)(g_aoh + ob1 + c) = pack2(h2, h3);
        *(unsigned*)(g_aol + ob0 + c) = pack2(__float2half_rn(v0 - __half2float(h0)),
                                              __float2half_rn(v1 - __half2float(h1)));
        *(unsigned*)(g_aol + ob1 + c) = pack2(__float2half_rn(v2 - __half2float(h2)),
                                              __float2half_rn(v3 - __half2float(h3)));
    }
}

// ---------------- host launcher ----------------
extern "C" void kernel_launch(void* const* d_in, const int* in_sizes, int n_in,
                              void* d_out, int out_size) {
    (void)in_sizes; (void)n_in; (void)out_size;
    const float* x    = (const float*)d_in[0];
    const float* Wqkv = (const float*)d_in[1];
    const float* bqkv = (const float*)d_in[2];
    const float* qn_w = (const float*)d_in[3];
    const float* kn_w = (const float*)d_in[4];
    const float* Wout = (const float*)d_in[5];
    const float* bout = (const float*)d_in[6];
    float* out = (float*)d_out;

    // [0] convert x (hi) + fused RoPE table
    k_split_x<<<(MROWS * D_ / 4) / 256, 256>>>(x, MROWS * D_ / 4);
    // [1] convert Wqkv (hi)
    k_split_w<<<(D_ * N3D / 4) / 256, 256>>>(Wqkv, 1, D_ * N3D / 4);

    // [2] QKV projection (pure fp16) + fused bias/rmsnorm/rope epilogue
    cudaFuncSetAttribute(k_gemm<0>, cudaFuncAttributeMaxDynamicSharedMemorySize, GEMM_SMEM);
    k_gemm<0><<<dim3(N3D / 128, MROWS / 256), 512, GEMM_SMEM>>>(bqkv, qn_w, kn_w, nullptr,
                                                                MROWS, N3D, D_);

    // [3] attention (ncu capture index) — fp16 MMA, exp2-domain fp32 softmax
    cudaFuncSetAttribute(k_attn, cudaFuncAttributeMaxDynamicSharedMemorySize, ATT_SMEM);
    k_attn<<<dim3(L_ / 128, B_ * H_), 256, ATT_SMEM>>>();

    // [4] convert Wout (hi; independent of attention, overlaps its tail)
    k_split_w<<<(D_ * D_ / 4) / 256, 256>>>(Wout, 2, D_ * D_ / 4);

    // [5] output projection (2-term: input residual kept) + bias -> d_out
    cudaFuncSetAttribute(k_gemm<1>, cudaFuncAttributeMaxDynamicSharedMemorySize, GEMM_SMEM);
    k_gemm<1><<<dim3(D_ / 128, MROWS / 256), 512, GEMM_SMEM>>>(bout, qn_w, kn_w, out,
                                                               MROWS, D_, D_);
}